// round 7
// baseline (speedup 1.0000x reference)
#include <cuda_runtime.h>
#include <cuda_bf16.h>
#include <cstdint>

#define N_NODES 100000
#define N_EDGES 500000
#define ET 3
#define C 128
#define NC (N_NODES * C)
#define LN_EPS 1e-5f
#define L2_EPS 1e-12f

#define PITCH 40                   // halves per smem row (bank-conflict-free)
#define CHB 10240                  // bytes per 128x32 bf16 plane chunk (128*PITCH*2)

// ---------------- scratch (static device globals; no allocation) ----------------
__device__ float g_m0[NC];
__device__ float g_m1[NC];
__device__ float g_m2[NC];
__device__ float g_hf[NC];
__device__ __nv_bfloat16 g_aggh[3 * NC];
__device__ __nv_bfloat16 g_aggl[3 * NC];
__device__ __nv_bfloat16 g_hh[NC];
__device__ __nv_bfloat16 g_hl[NC];
__device__ __nv_bfloat16 g_wth[17 * C * C];
__device__ __nv_bfloat16 g_wtl[17 * C * C];
__device__ float g_wsum[2 * C * C];
__device__ float g_bsum[2 * C];
__device__ float g_invdeg[ET * N_NODES];
__device__ int g_cnt[ET * N_NODES];
__device__ int g_cur[ET * N_NODES];
__device__ int g_rowptr[ET * (N_NODES + 1)];
__device__ int g_col[ET * N_EDGES];
__device__ int g_bofs[ET * 128];

// ---------------- helpers ----------------
__device__ __forceinline__ uint32_t smem_u32(const void* p) {
    uint32_t a;
    asm("{ .reg .u64 t; cvta.to.shared.u64 t, %1; cvt.u32.u64 %0, t; }" : "=r"(a) : "l"(p));
    return a;
}
__device__ __forceinline__ void cp16(uint32_t dst, const void* src, int srcsize) {
    asm volatile("cp.async.cg.shared.global [%0], [%1], 16, %2;"
                 :: "r"(dst), "l"(src), "r"(srcsize));
}
#define CP_COMMIT() asm volatile("cp.async.commit_group;" ::: "memory")
#define CP_WAIT1()  asm volatile("cp.async.wait_group 1;" ::: "memory")
#define CP_WAIT0()  asm volatile("cp.async.wait_group 0;" ::: "memory")

__device__ __forceinline__ void mma_bf16(float* d, const uint32_t* a, uint32_t b0, uint32_t b1) {
    asm volatile(
        "mma.sync.aligned.m16n8k16.row.col.f32.bf16.bf16.f32 "
        "{%0,%1,%2,%3}, {%4,%5,%6,%7}, {%8,%9}, {%0,%1,%2,%3};"
        : "+f"(d[0]), "+f"(d[1]), "+f"(d[2]), "+f"(d[3])
        : "r"(a[0]), "r"(a[1]), "r"(a[2]), "r"(a[3]), "r"(b0), "r"(b1));
}
__device__ __forceinline__ void split2(float x, __nv_bfloat16& hi, __nv_bfloat16& lo) {
    hi = __float2bfloat16_rn(x);
    lo = __float2bfloat16_rn(x - __bfloat162float(hi));
}
__device__ __forceinline__ void split_store4(__nv_bfloat16* hi, __nv_bfloat16* lo,
                                             int idx, float4 v) {
    __nv_bfloat16 hx, lx, hy, ly, hz, lz, hw, lw;
    split2(v.x, hx, lx); split2(v.y, hy, ly);
    split2(v.z, hz, lz); split2(v.w, hw, lw);
    __nv_bfloat162 h01; h01.x = hx; h01.y = hy;
    __nv_bfloat162 h23; h23.x = hz; h23.y = hw;
    __nv_bfloat162 l01; l01.x = lx; l01.y = ly;
    __nv_bfloat162 l23; l23.x = lz; l23.y = lw;
    *reinterpret_cast<__nv_bfloat162*>(&hi[idx]) = h01;
    *reinterpret_cast<__nv_bfloat162*>(&hi[idx + 2]) = h23;
    *reinterpret_cast<__nv_bfloat162*>(&lo[idx]) = l01;
    *reinterpret_cast<__nv_bfloat162*>(&lo[idx + 2]) = l23;
}

// one 128x128x32 chunk stage (3-term split-bf16)
__device__ __forceinline__ void mma_stage(
    const __nv_bfloat16* __restrict__ Ahi, const __nv_bfloat16* __restrict__ Alo,
    const __nv_bfloat16* __restrict__ Bhi, const __nv_bfloat16* __restrict__ Blo,
    int wm, int wn, int g, int tg, float (*acc)[8][4])
{
    #pragma unroll
    for (int ks = 0; ks < 2; ks++) {
        int kk = ks * 16;
        uint32_t ah[2][4], al[2][4];
        #pragma unroll
        for (int mi = 0; mi < 2; mi++) {
            int m = wm * 32 + mi * 16 + g;
            int base = m * PITCH + kk + 2 * tg;
            ah[mi][0] = *reinterpret_cast<const uint32_t*>(&Ahi[base]);
            ah[mi][1] = *reinterpret_cast<const uint32_t*>(&Ahi[base + 8 * PITCH]);
            ah[mi][2] = *reinterpret_cast<const uint32_t*>(&Ahi[base + 8]);
            ah[mi][3] = *reinterpret_cast<const uint32_t*>(&Ahi[base + 8 * PITCH + 8]);
            al[mi][0] = *reinterpret_cast<const uint32_t*>(&Alo[base]);
            al[mi][1] = *reinterpret_cast<const uint32_t*>(&Alo[base + 8 * PITCH]);
            al[mi][2] = *reinterpret_cast<const uint32_t*>(&Alo[base + 8]);
            al[mi][3] = *reinterpret_cast<const uint32_t*>(&Alo[base + 8 * PITCH + 8]);
        }
        #pragma unroll
        for (int ni = 0; ni < 8; ni++) {
            int n = wn * 64 + ni * 8 + g;
            int bbase = n * PITCH + kk + 2 * tg;
            uint32_t bh0 = *reinterpret_cast<const uint32_t*>(&Bhi[bbase]);
            uint32_t bh1 = *reinterpret_cast<const uint32_t*>(&Bhi[bbase + 8]);
            uint32_t bl0 = *reinterpret_cast<const uint32_t*>(&Blo[bbase]);
            uint32_t bl1 = *reinterpret_cast<const uint32_t*>(&Blo[bbase + 8]);
            #pragma unroll
            for (int mi = 0; mi < 2; mi++) {
                mma_bf16(acc[mi][ni], ah[mi], bh0, bh1);
                mma_bf16(acc[mi][ni], ah[mi], bl0, bl1);
                mma_bf16(acc[mi][ni], al[mi], bh0, bh1);
            }
        }
    }
}

// fragment-domain LayerNorm + store (fp32 out + optional bf16 hi/lo planes)
__device__ __forceinline__ void frag_ln_store(
    float (*acc)[8][4], char* redmem, int t, int wm, int wn, int g, int tg, int row0,
    const float* __restrict__ lng, const float* __restrict__ lnb,
    float* __restrict__ outf, __nv_bfloat16* __restrict__ ohh, __nv_bfloat16* __restrict__ ohl)
{
    float* red_s = (float*)redmem;   // [128][2]
    float* red_q = red_s + 256;      // [128][2]
    float* rmean = red_q + 256;      // [128]
    float* rstdv = rmean + 128;      // [128]
    float s0[2] = {0.f, 0.f}, q0[2] = {0.f, 0.f};
    float s1[2] = {0.f, 0.f}, q1[2] = {0.f, 0.f};
    #pragma unroll
    for (int mi = 0; mi < 2; mi++)
        #pragma unroll
        for (int ni = 0; ni < 8; ni++) {
            s0[mi] += acc[mi][ni][0] + acc[mi][ni][1];
            q0[mi] += acc[mi][ni][0] * acc[mi][ni][0] + acc[mi][ni][1] * acc[mi][ni][1];
            s1[mi] += acc[mi][ni][2] + acc[mi][ni][3];
            q1[mi] += acc[mi][ni][2] * acc[mi][ni][2] + acc[mi][ni][3] * acc[mi][ni][3];
        }
    #pragma unroll
    for (int mi = 0; mi < 2; mi++) {
        s0[mi] += __shfl_xor_sync(0xffffffffu, s0[mi], 1);
        s0[mi] += __shfl_xor_sync(0xffffffffu, s0[mi], 2);
        q0[mi] += __shfl_xor_sync(0xffffffffu, q0[mi], 1);
        q0[mi] += __shfl_xor_sync(0xffffffffu, q0[mi], 2);
        s1[mi] += __shfl_xor_sync(0xffffffffu, s1[mi], 1);
        s1[mi] += __shfl_xor_sync(0xffffffffu, s1[mi], 2);
        q1[mi] += __shfl_xor_sync(0xffffffffu, q1[mi], 1);
        q1[mi] += __shfl_xor_sync(0xffffffffu, q1[mi], 2);
    }
    if (tg == 0) {
        #pragma unroll
        for (int mi = 0; mi < 2; mi++) {
            int lr = wm * 32 + mi * 16 + g;
            red_s[lr * 2 + wn] = s0[mi];
            red_q[lr * 2 + wn] = q0[mi];
            red_s[(lr + 8) * 2 + wn] = s1[mi];
            red_q[(lr + 8) * 2 + wn] = q1[mi];
        }
    }
    __syncthreads();
    if (t < 128) {
        float ssum = red_s[t * 2] + red_s[t * 2 + 1];
        float qsum = red_q[t * 2] + red_q[t * 2 + 1];
        float mean = ssum * (1.f / 128.f);
        float var = qsum * (1.f / 128.f) - mean * mean;
        rmean[t] = mean;
        rstdv[t] = rsqrtf(fmaxf(var, 0.f) + LN_EPS);
    }
    __syncthreads();
    #pragma unroll
    for (int mi = 0; mi < 2; mi++) {
        int lr0 = wm * 32 + mi * 16 + g;
        int r0 = row0 + lr0, r1 = r0 + 8;
        float m0 = rmean[lr0], d0 = rstdv[lr0];
        float m1 = rmean[lr0 + 8], d1 = rstdv[lr0 + 8];
        #pragma unroll
        for (int ni = 0; ni < 8; ni++) {
            int coln = wn * 64 + ni * 8 + tg * 2;
            float2 gv = *reinterpret_cast<const float2*>(&lng[coln]);
            float2 bb = *reinterpret_cast<const float2*>(&lnb[coln]);
            if (r0 < N_NODES) {
                float2 o;
                o.x = (acc[mi][ni][0] - m0) * d0 * gv.x + bb.x;
                o.y = (acc[mi][ni][1] - m0) * d0 * gv.y + bb.y;
                *reinterpret_cast<float2*>(&outf[(size_t)r0 * C + coln]) = o;
                __nv_bfloat162 hh, ll;
                split2(o.x, hh.x, ll.x); split2(o.y, hh.y, ll.y);
                *reinterpret_cast<__nv_bfloat162*>(&ohh[(size_t)r0 * C + coln]) = hh;
                *reinterpret_cast<__nv_bfloat162*>(&ohl[(size_t)r0 * C + coln]) = ll;
            }
            if (r1 < N_NODES) {
                float2 o;
                o.x = (acc[mi][ni][2] - m1) * d1 * gv.x + bb.x;
                o.y = (acc[mi][ni][3] - m1) * d1 * gv.y + bb.y;
                *reinterpret_cast<float2*>(&outf[(size_t)r1 * C + coln]) = o;
                __nv_bfloat162 hh, ll;
                split2(o.x, hh.x, ll.x); split2(o.y, hh.y, ll.y);
                *reinterpret_cast<__nv_bfloat162*>(&ohh[(size_t)r1 * C + coln]) = hh;
                *reinterpret_cast<__nv_bfloat162*>(&ohl[(size_t)r1 * C + coln]) = ll;
            }
        }
    }
}

// ---------------- CSR build ----------------
__global__ void k_zero_int() {
    int i = blockIdx.x * blockDim.x + threadIdx.x;
    if (i < ET * N_NODES) { g_cnt[i] = 0; g_cur[i] = 0; }
}
__global__ void k_hist(const int* __restrict__ edges) {
    int i = blockIdx.x * blockDim.x + threadIdx.x;
    if (i >= ET * N_EDGES) return;
    int t = i / N_EDGES, e = i - t * N_EDGES;
    int dst = edges[(t * 2 + 1) * N_EDGES + e];
    atomicAdd(&g_cnt[t * N_NODES + dst], 1);
}
__global__ void k_scan1() {
    int t = blockIdx.y;
    int i = blockIdx.x * 1024 + threadIdx.x;
    __shared__ int sm[1024];
    int v = (i < N_NODES) ? g_cnt[t * N_NODES + i] : 0;
    sm[threadIdx.x] = v;
    __syncthreads();
    for (int off = 1; off < 1024; off <<= 1) {
        int add = (threadIdx.x >= off) ? sm[threadIdx.x - off] : 0;
        __syncthreads();
        sm[threadIdx.x] += add;
        __syncthreads();
    }
    if (i < N_NODES) g_rowptr[t * (N_NODES + 1) + i] = sm[threadIdx.x] - v;
    if (threadIdx.x == 1023) g_bofs[t * 128 + blockIdx.x] = sm[1023];
}
__global__ void k_scan2() {
    int t = threadIdx.x;
    if (t >= ET) return;
    int nb = (N_NODES + 1023) / 1024;
    int run = 0;
    for (int b = 0; b < nb; b++) { int v = g_bofs[t * 128 + b]; g_bofs[t * 128 + b] = run; run += v; }
    g_rowptr[t * (N_NODES + 1) + N_NODES] = run;
}
__global__ void k_scan3() {
    int t = blockIdx.y;
    int i = blockIdx.x * 1024 + threadIdx.x;
    if (i < N_NODES) g_rowptr[t * (N_NODES + 1) + i] += g_bofs[t * 128 + blockIdx.x];
}
__global__ void k_invdeg() {
    int i = blockIdx.x * blockDim.x + threadIdx.x;
    if (i < ET * N_NODES) {
        int c = g_cnt[i];
        g_invdeg[i] = 1.0f / (float)(c > 1 ? c : 1);
    }
}
__global__ void k_scatter(const int* __restrict__ edges) {
    int i = blockIdx.x * blockDim.x + threadIdx.x;
    if (i >= ET * N_EDGES) return;
    int t = i / N_EDGES, e = i - t * N_EDGES;
    int src = edges[t * 2 * N_EDGES + e];
    int dst = edges[(t * 2 + 1) * N_EDGES + e];
    int pos = g_rowptr[t * (N_NODES + 1) + dst] + atomicAdd(&g_cur[t * N_NODES + dst], 1);
    g_col[t * N_EDGES + pos] = src;
}

// ---------------- weight pre-sum (fp32) ----------------
__global__ void k_wsum(const float* __restrict__ Wr, const float* __restrict__ bl) {
    int i = blockIdx.x * blockDim.x + threadIdx.x;
    if (i < 2 * C * C) {
        int l = i / (C * C), idx = i - l * (C * C);
        g_wsum[i] = Wr[(l * 3 + 0) * C * C + idx] + Wr[(l * 3 + 1) * C * C + idx]
                  + Wr[(l * 3 + 2) * C * C + idx];
    }
    if (i < 2 * C) {
        int l = i / C, cc = i - l * C;
        g_bsum[i] = bl[(l * 3 + 0) * C + cc] + bl[(l * 3 + 1) * C + cc] + bl[(l * 3 + 2) * C + cc];
    }
}

// ---------------- transpose + split all 17 weight matrices into bf16 planes ----------------
// mats: 0-2 Wp, 3-5 Wl0, 6-8 Wr0, 9-14 Wl, 15-16 wsum.  out[m][n][k] = split(W[m][k][n])
__global__ void k_wprep(const float* __restrict__ Wp, const float* __restrict__ Wl0,
                        const float* __restrict__ Wr0, const float* __restrict__ Wl) {
    int m = blockIdx.y;
    const float* src;
    if (m < 3) src = Wp + (size_t)m * C * C;
    else if (m < 6) src = Wl0 + (size_t)(m - 3) * C * C;
    else if (m < 9) src = Wr0 + (size_t)(m - 6) * C * C;
    else if (m < 15) src = Wl + (size_t)(m - 9) * C * C;
    else src = g_wsum + (size_t)(m - 15) * C * C;
    __shared__ float tile[32][33];
    int txt = (blockIdx.x & 3) * 32, tyt = (blockIdx.x >> 2) * 32;
    int tx = threadIdx.x, ty = threadIdx.y;
    #pragma unroll
    for (int i = 0; i < 4; i++)
        tile[ty + i * 8][tx] = src[(size_t)(tyt + ty + i * 8) * C + txt + tx];
    __syncthreads();
    #pragma unroll
    for (int i = 0; i < 4; i++) {
        int n = txt + ty + i * 8, k = tyt + tx;
        float v = tile[tx][ty + i * 8];
        __nv_bfloat16 hi, lo; split2(v, hi, lo);
        g_wth[(size_t)m * C * C + n * C + k] = hi;
        g_wtl[(size_t)m * C * C + n * C + k] = lo;
    }
}

// ---------------- fused 3-type mean aggregation -> bf16 hi/lo planes ----------------
__global__ void k_agg3(const float* __restrict__ f0, const float* __restrict__ f1,
                       const float* __restrict__ f2) {
    int w = (blockIdx.x * blockDim.x + threadIdx.x) >> 5;
    int lane = threadIdx.x & 31;
    if (w >= N_NODES) return;
    const float* feats[3] = {f0, f1, f2};
    #pragma unroll
    for (int t = 0; t < 3; t++) {
        const int* rp = &g_rowptr[t * (N_NODES + 1)];
        int s = rp[w], e = rp[w + 1];
        const int* col = &g_col[t * N_EDGES];
        const float* feat = feats[t];
        float4 acc = make_float4(0.f, 0.f, 0.f, 0.f);
        for (int j = s; j < e; j++) {
            int src = col[j];
            float4 v = *reinterpret_cast<const float4*>(&feat[(size_t)src * C + lane * 4]);
            acc.x += v.x; acc.y += v.y; acc.z += v.z; acc.w += v.w;
        }
        float inv = g_invdeg[t * N_NODES + w];
        acc.x *= inv; acc.y *= inv; acc.z *= inv; acc.w *= inv;
        __nv_bfloat162 hA, hB, lA, lB;
        split2(acc.x, hA.x, lA.x); split2(acc.y, hA.y, lA.y);
        split2(acc.z, hB.x, lB.x); split2(acc.w, hB.y, lB.y);
        size_t off = (size_t)t * NC + (size_t)w * C + lane * 4;
        uint2 uh, ul;
        uh.x = *reinterpret_cast<uint32_t*>(&hA); uh.y = *reinterpret_cast<uint32_t*>(&hB);
        ul.x = *reinterpret_cast<uint32_t*>(&lA); ul.y = *reinterpret_cast<uint32_t*>(&lB);
        *reinterpret_cast<uint2*>(&g_aggh[off]) = uh;
        *reinterpret_cast<uint2*>(&g_aggl[off]) = ul;
    }
}

// ---------------- layer-0 projection: msg_t = relu(x@Wp_t + bp_t), x resident ----------------
#define SMEM_PROJ_BYTES (2 * 2 * CHB + 8 * CHB)   // ring(2 x BhBl) + resident x planes
__global__ __launch_bounds__(256) void k_proj3(
    const float* __restrict__ x, const float* __restrict__ bp,
    float* __restrict__ m0, float* __restrict__ m1, float* __restrict__ m2)
{
    extern __shared__ __align__(16) char smem[];
    uint32_t sb = smem_u32(smem);
    const uint32_t RB = 2 * 2 * CHB;      // resident base
    int t = threadIdx.x, lane = t & 31, wid = t >> 5;
    int g = lane >> 2, tg = lane & 3;
    int wm = wid & 3, wn = wid >> 2;
    int row0 = blockIdx.x * 128;
    int ar = t >> 1, sel = t & 1;
    uint32_t soff = ar * 80 + sel * 32;
    int gr = row0 + ar;
    bool valid = gr < N_NODES;
    int kq = sel * 16;

    // resident x planes (4 chunks hi, 4 lo)
    #pragma unroll
    for (int c = 0; c < 4; c++)
        #pragma unroll
        for (int q = 0; q < 4; q++) {
            float4 v = valid ? *reinterpret_cast<const float4*>(&x[(size_t)gr * C + c * 32 + kq + q * 4])
                             : make_float4(0.f, 0.f, 0.f, 0.f);
            int idx = ar * PITCH + kq + q * 4;
            split_store4((__nv_bfloat16*)(smem + RB + c * CHB),
                         (__nv_bfloat16*)(smem + RB + 4 * CHB + c * CHB), idx, v);
        }

    auto issueB = [&](int s) {
        uint32_t slot = sb + (s & 1) * (2 * CHB);
        int tt = s >> 2, kc = (s & 3) * 32;
        size_t be = (size_t)tt * C * C + (size_t)ar * C + kc + sel * 16;
        cp16(slot + soff, g_wth + be, 16);
        cp16(slot + soff + 16, g_wth + be + 8, 16);
        cp16(slot + CHB + soff, g_wtl + be, 16);
        cp16(slot + CHB + soff + 16, g_wtl + be + 8, 16);
        CP_COMMIT();
    };

    float acc[2][8][4];
    float* msgs[3] = {m0, m1, m2};

    issueB(0);
    for (int s = 0; s < 12; s++) {
        if (s + 1 < 12) { issueB(s + 1); CP_WAIT1(); } else CP_WAIT0();
        __syncthreads();
        if ((s & 3) == 0) {
            #pragma unroll
            for (int mi = 0; mi < 2; mi++)
                #pragma unroll
                for (int ni = 0; ni < 8; ni++)
                    #pragma unroll
                    for (int r = 0; r < 4; r++) acc[mi][ni][r] = 0.f;
        }
        char* sl = smem + (s & 1) * (2 * CHB);
        mma_stage((__nv_bfloat16*)(smem + RB + (s & 3) * CHB),
                  (__nv_bfloat16*)(smem + RB + 4 * CHB + (s & 3) * CHB),
                  (__nv_bfloat16*)sl, (__nv_bfloat16*)(sl + CHB), wm, wn, g, tg, acc);
        __syncthreads();
        if ((s & 3) == 3) {
            int tt = s >> 2;
            const float* bias = bp + tt * C;
            float* out = msgs[tt];
            #pragma unroll
            for (int mi = 0; mi < 2; mi++) {
                int r0 = row0 + wm * 32 + mi * 16 + g, r1 = r0 + 8;
                #pragma unroll
                for (int ni = 0; ni < 8; ni++) {
                    int coln = wn * 64 + ni * 8 + tg * 2;
                    float2 bv = *reinterpret_cast<const float2*>(&bias[coln]);
                    float2 o0, o1;
                    o0.x = fmaxf(acc[mi][ni][0] + bv.x, 0.f);
                    o0.y = fmaxf(acc[mi][ni][1] + bv.y, 0.f);
                    o1.x = fmaxf(acc[mi][ni][2] + bv.x, 0.f);
                    o1.y = fmaxf(acc[mi][ni][3] + bv.y, 0.f);
                    if (r0 < N_NODES) *reinterpret_cast<float2*>(&out[(size_t)r0 * C + coln]) = o0;
                    if (r1 < N_NODES) *reinterpret_cast<float2*>(&out[(size_t)r1 * C + coln]) = o1;
                }
            }
        }
    }
}

// ---------------- layer-0 dual GEMM + norm-accum + relu/3 + LN -> h (+planes) ----------------
// smem: ring 2 x (Ahi,Alo,Bhi,Blo) = 81920 | resident x planes 81920 | red 3072
#define SMEM_DUAL_BYTES (2 * 4 * CHB + 8 * CHB + 3072)
__global__ __launch_bounds__(256, 1) void k_dual0(
    const float* __restrict__ x, const float* __restrict__ bl0,
    const float* __restrict__ lng, const float* __restrict__ lnb)
{
    extern __shared__ __align__(16) char smem[];
    uint32_t sb = smem_u32(smem);
    const uint32_t RB = 2 * 4 * CHB;
    char* redmem = smem + RB + 8 * CHB;
    int t = threadIdx.x, lane = t & 31, wid = t >> 5;
    int g = lane >> 2, tg = lane & 3;
    int wm = wid & 3, wn = wid >> 2;
    int row0 = blockIdx.x * 128;
    int ar = t >> 1, sel = t & 1;
    uint32_t soff = ar * 80 + sel * 32;
    int gr = row0 + ar;
    bool valid = gr < N_NODES;
    int grc = valid ? gr : (N_NODES - 1);
    int ssz = valid ? 16 : 0;
    int kq = sel * 16;

    // resident x planes
    #pragma unroll
    for (int c = 0; c < 4; c++)
        #pragma unroll
        for (int q = 0; q < 4; q++) {
            float4 v = valid ? *reinterpret_cast<const float4*>(&x[(size_t)gr * C + c * 32 + kq + q * 4])
                             : make_float4(0.f, 0.f, 0.f, 0.f);
            int idx = ar * PITCH + kq + q * 4;
            split_store4((__nv_bfloat16*)(smem + RB + c * CHB),
                         (__nv_bfloat16*)(smem + RB + 4 * CHB + c * CHB), idx, v);
        }

    auto issue = [&](int st) {
        uint32_t slot = sb + (st & 1) * (4 * CHB);
        int tt = st >> 3, j = st & 7;
        if (j < 4) {
            size_t ae = (size_t)tt * NC + (size_t)grc * C + j * 32 + sel * 16;
            cp16(slot + soff, g_aggh + ae, ssz);
            cp16(slot + soff + 16, g_aggh + ae + 8, ssz);
            cp16(slot + CHB + soff, g_aggl + ae, ssz);
            cp16(slot + CHB + soff + 16, g_aggl + ae + 8, ssz);
        }
        int mat = (j < 4) ? (3 + tt) : (6 + tt);
        int kc = (j & 3) * 32;
        size_t be = (size_t)mat * C * C + (size_t)ar * C + kc + sel * 16;
        cp16(slot + 2 * CHB + soff, g_wth + be, 16);
        cp16(slot + 2 * CHB + soff + 16, g_wth + be + 8, 16);
        cp16(slot + 3 * CHB + soff, g_wtl + be, 16);
        cp16(slot + 3 * CHB + soff + 16, g_wtl + be + 8, 16);
        CP_COMMIT();
    };

    float acc[2][8][4], accN[2][8][4];
    #pragma unroll
    for (int mi = 0; mi < 2; mi++)
        #pragma unroll
        for (int ni = 0; ni < 8; ni++)
            #pragma unroll
            for (int r = 0; r < 4; r++) accN[mi][ni][r] = 0.f;

    issue(0);
    for (int st = 0; st < 24; st++) {
        if (st + 1 < 24) { issue(st + 1); CP_WAIT1(); } else CP_WAIT0();
        __syncthreads();
        int tt = st >> 3, j = st & 7;
        if (j == 0) {
            #pragma unroll
            for (int mi = 0; mi < 2; mi++)
                #pragma unroll
                for (int ni = 0; ni < 8; ni++)
                    #pragma unroll
                    for (int r = 0; r < 4; r++) acc[mi][ni][r] = 0.f;
        }
        char* sl = smem + (st & 1) * (4 * CHB);
        const __nv_bfloat16 *Ah, *Al;
        if (j < 4) { Ah = (__nv_bfloat16*)sl; Al = (__nv_bfloat16*)(sl + CHB); }
        else {
            Ah = (__nv_bfloat16*)(smem + RB + (j - 4) * CHB);
            Al = (__nv_bfloat16*)(smem + RB + 4 * CHB + (j - 4) * CHB);
        }
        mma_stage(Ah, Al, (__nv_bfloat16*)(sl + 2 * CHB), (__nv_bfloat16*)(sl + 3 * CHB),
                  wm, wn, g, tg, acc);
        __syncthreads();
        if (j == 7) {
            // bias + per-row L2 norm + accumulate
            const float* bias = bl0 + tt * C;
            #pragma unroll
            for (int ni = 0; ni < 8; ni++) {
                int coln = wn * 64 + ni * 8 + tg * 2;
                float2 bv = *reinterpret_cast<const float2*>(&bias[coln]);
                #pragma unroll
                for (int mi = 0; mi < 2; mi++) {
                    acc[mi][ni][0] += bv.x; acc[mi][ni][1] += bv.y;
                    acc[mi][ni][2] += bv.x; acc[mi][ni][3] += bv.y;
                }
            }
            float* red = (float*)redmem;     // [128][2]
            float* invn = red + 256;         // [128]
            float ss0[2] = {0.f, 0.f}, ss1[2] = {0.f, 0.f};
            #pragma unroll
            for (int mi = 0; mi < 2; mi++)
                #pragma unroll
                for (int ni = 0; ni < 8; ni++) {
                    ss0[mi] += acc[mi][ni][0] * acc[mi][ni][0] + acc[mi][ni][1] * acc[mi][ni][1];
                    ss1[mi] += acc[mi][ni][2] * acc[mi][ni][2] + acc[mi][ni][3] * acc[mi][ni][3];
                }
            #pragma unroll
            for (int mi = 0; mi < 2; mi++) {
                ss0[mi] += __shfl_xor_sync(0xffffffffu, ss0[mi], 1);
                ss0[mi] += __shfl_xor_sync(0xffffffffu, ss0[mi], 2);
                ss1[mi] += __shfl_xor_sync(0xffffffffu, ss1[mi], 1);
                ss1[mi] += __shfl_xor_sync(0xffffffffu, ss1[mi], 2);
            }
            if (tg == 0) {
                #pragma unroll
                for (int mi = 0; mi < 2; mi++) {
                    red[(wm * 32 + mi * 16 + g) * 2 + wn] = ss0[mi];
                    red[(wm * 32 + mi * 16 + 8 + g) * 2 + wn] = ss1[mi];
                }
            }
            __syncthreads();
            if (t < 128) invn[t] = 1.f / fmaxf(sqrtf(red[t * 2] + red[t * 2 + 1]), L2_EPS);
            __syncthreads();
            #pragma unroll
            for (int mi = 0; mi < 2; mi++) {
                int lr0 = wm * 32 + mi * 16 + g;
                float i0 = invn[lr0], i1 = invn[lr0 + 8];
                #pragma unroll
                for (int ni = 0; ni < 8; ni++) {
                    accN[mi][ni][0] += acc[mi][ni][0] * i0;
                    accN[mi][ni][1] += acc[mi][ni][1] * i0;
                    accN[mi][ni][2] += acc[mi][ni][2] * i1;
                    accN[mi][ni][3] += acc[mi][ni][3] * i1;
                }
            }
            __syncthreads();
        }
    }

    // h = LN(relu(accN/3)) + planes
    #pragma unroll
    for (int mi = 0; mi < 2; mi++)
        #pragma unroll
        for (int ni = 0; ni < 8; ni++)
            #pragma unroll
            for (int r = 0; r < 4; r++)
                accN[mi][ni][r] = fmaxf(accN[mi][ni][r] * (1.f / 3.f), 0.f);
    frag_ln_store(accN, redmem, t, wm, wn, g, tg, row0, lng, lnb, g_hf, g_hh, g_hl);
}

// ---------------- generic K=512 GEMM (layers 1..2), streamed planes ----------------
// mode 2: out = (acc+bias)/3 (fp32)   mode 3: h = LN(relu((acc+bias)/3)) + planes
#define SMEM_MMA_BYTES (2 * 4 * CHB)     // 81920
__global__ __launch_bounds__(256, 2) void k_mma(
    const __nv_bfloat16* __restrict__ A0h, const __nv_bfloat16* __restrict__ A0l,
    const __nv_bfloat16* __restrict__ A1h, const __nv_bfloat16* __restrict__ A1l,
    const __nv_bfloat16* __restrict__ A2h, const __nv_bfloat16* __restrict__ A2l,
    const __nv_bfloat16* __restrict__ A3h, const __nv_bfloat16* __restrict__ A3l,
    int m0, int m1, int m2, int m3,
    const float* __restrict__ bias, const float* __restrict__ lng,
    const float* __restrict__ lnb, float* __restrict__ outf, int mode)
{
    extern __shared__ __align__(16) char smem[];
    uint32_t sb = smem_u32(smem);
    int t = threadIdx.x, lane = t & 31, wid = t >> 5;
    int g = lane >> 2, tg = lane & 3;
    int wm = wid & 3, wn = wid >> 2;
    int row0 = blockIdx.x * 128;
    int ar = t >> 1, sel = t & 1;
    uint32_t soff = ar * 80 + sel * 32;
    int gr = row0 + ar;
    bool valid = gr < N_NODES;
    int grc = valid ? gr : (N_NODES - 1);
    int ssz = valid ? 16 : 0;

    const __nv_bfloat16* Ah[4] = {A0h, A1h, A2h, A3h};
    const __nv_bfloat16* Al[4] = {A0l, A1l, A2l, A3l};
    int mats[4] = {m0, m1, m2, m3};

    auto issue = [&](int s) {
        uint32_t slot = sb + (s & 1) * (4 * CHB);
        int c = s >> 2, kc = (s & 3) * 32;
        size_t ae = (size_t)grc * C + kc + sel * 16;
        cp16(slot + soff, Ah[c] + ae, ssz);
        cp16(slot + soff + 16, Ah[c] + ae + 8, ssz);
        cp16(slot + CHB + soff, Al[c] + ae, ssz);
        cp16(slot + CHB + soff + 16, Al[c] + ae + 8, ssz);
        size_t be = (size_t)mats[c] * C * C + (size_t)ar * C + kc + sel * 16;
        cp16(slot + 2 * CHB + soff, g_wth + be, 16);
        cp16(slot + 2 * CHB + soff + 16, g_wth + be + 8, 16);
        cp16(slot + 3 * CHB + soff, g_wtl + be, 16);
        cp16(slot + 3 * CHB + soff + 16, g_wtl + be + 8, 16);
        CP_COMMIT();
    };

    float acc[2][8][4];
    #pragma unroll
    for (int mi = 0; mi < 2; mi++)
        #pragma unroll
        for (int ni = 0; ni < 8; ni++)
            #pragma unroll
            for (int r = 0; r < 4; r++) acc[mi][ni][r] = 0.f;

    issue(0);
    for (int s = 0; s < 16; s++) {
        if (s + 1 < 16) { issue(s + 1); CP_WAIT1(); } else CP_WAIT0();
        __syncthreads();
        char* sl = smem + (s & 1) * (4 * CHB);
        mma_stage((__nv_bfloat16*)sl, (__nv_bfloat16*)(sl + CHB),
                  (__nv_bfloat16*)(sl + 2 * CHB), (__nv_bfloat16*)(sl + 3 * CHB),
                  wm, wn, g, tg, acc);
        __syncthreads();
    }

    const float sc = 1.f / 3.f;
    #pragma unroll
    for (int ni = 0; ni < 8; ni++) {
        int coln = wn * 64 + ni * 8 + tg * 2;
        float2 bv = *reinterpret_cast<const float2*>(&bias[coln]);
        #pragma unroll
        for (int mi = 0; mi < 2; mi++) {
            acc[mi][ni][0] = (acc[mi][ni][0] + bv.x) * sc;
            acc[mi][ni][1] = (acc[mi][ni][1] + bv.y) * sc;
            acc[mi][ni][2] = (acc[mi][ni][2] + bv.x) * sc;
            acc[mi][ni][3] = (acc[mi][ni][3] + bv.y) * sc;
            if (mode == 3) {
                acc[mi][ni][0] = fmaxf(acc[mi][ni][0], 0.f);
                acc[mi][ni][1] = fmaxf(acc[mi][ni][1], 0.f);
                acc[mi][ni][2] = fmaxf(acc[mi][ni][2], 0.f);
                acc[mi][ni][3] = fmaxf(acc[mi][ni][3], 0.f);
            }
        }
    }

    if (mode == 3) {
        frag_ln_store(acc, smem, t, wm, wn, g, tg, row0, lng, lnb, g_hf, g_hh, g_hl);
    } else {
        #pragma unroll
        for (int mi = 0; mi < 2; mi++) {
            int r0 = row0 + wm * 32 + mi * 16 + g, r1 = r0 + 8;
            #pragma unroll
            for (int ni = 0; ni < 8; ni++) {
                int coln = wn * 64 + ni * 8 + tg * 2;
                if (r0 < N_NODES) {
                    float2 o; o.x = acc[mi][ni][0]; o.y = acc[mi][ni][1];
                    *reinterpret_cast<float2*>(&outf[(size_t)r0 * C + coln]) = o;
                }
                if (r1 < N_NODES) {
                    float2 o; o.x = acc[mi][ni][2]; o.y = acc[mi][ni][3];
                    *reinterpret_cast<float2*>(&outf[(size_t)r1 * C + coln]) = o;
                }
            }
        }
    }
}

// ---------------- host orchestration ----------------
extern "C" void kernel_launch(void* const* d_in, const int* in_sizes, int n_in,
                              void* d_out, int out_size) {
    const float* x    = (const float*)d_in[0];
    const int*   edges = (const int*)d_in[1];
    const float* Wp   = (const float*)d_in[2];
    const float* bp   = (const float*)d_in[3];
    const float* Wl0  = (const float*)d_in[4];
    const float* bl0  = (const float*)d_in[5];
    const float* Wr0  = (const float*)d_in[6];
    const float* Wl   = (const float*)d_in[7];
    const float* bl   = (const float*)d_in[8];
    const float* Wr   = (const float*)d_in[9];
    const float* ln_g = (const float*)d_in[10];
    const float* ln_b = (const float*)d_in[11];
    float* out = (float*)d_out;

    void* p;
    float *m0, *m1, *m2, *hf, *bsum;
    __nv_bfloat16 *aggh, *aggl, *hh, *hl;
    cudaGetSymbolAddress(&p, g_m0);   m0 = (float*)p;
    cudaGetSymbolAddress(&p, g_m1);   m1 = (float*)p;
    cudaGetSymbolAddress(&p, g_m2);   m2 = (float*)p;
    cudaGetSymbolAddress(&p, g_hf);   hf = (float*)p;
    cudaGetSymbolAddress(&p, g_bsum); bsum = (float*)p;
    cudaGetSymbolAddress(&p, g_aggh); aggh = (__nv_bfloat16*)p;
    cudaGetSymbolAddress(&p, g_aggl); aggl = (__nv_bfloat16*)p;
    cudaGetSymbolAddress(&p, g_hh);   hh = (__nv_bfloat16*)p;
    cudaGetSymbolAddress(&p, g_hl);   hl = (__nv_bfloat16*)p;

    cudaFuncSetAttribute(k_proj3, cudaFuncAttributeMaxDynamicSharedMemorySize, SMEM_PROJ_BYTES);
    cudaFuncSetAttribute(k_dual0, cudaFuncAttributeMaxDynamicSharedMemorySize, SMEM_DUAL_BYTES);
    cudaFuncSetAttribute(k_mma, cudaFuncAttributeMaxDynamicSharedMemorySize, SMEM_MMA_BYTES);

    int nbScan = (N_NODES + 1023) / 1024;
    dim3 gScan(nbScan, ET);
    int gMma = (N_NODES + 127) / 128;
    int gWarp = (N_NODES * 32 + 255) / 256;

    // CSR build + weight prep
    k_zero_int<<<(ET * N_NODES + 255) / 256, 256>>>();
    k_hist<<<(ET * N_EDGES + 255) / 256, 256>>>(edges);
    k_scan1<<<gScan, 1024>>>();
    k_scan2<<<1, 32>>>();
    k_scan3<<<gScan, 1024>>>();
    k_invdeg<<<(ET * N_NODES + 255) / 256, 256>>>();
    k_scatter<<<(ET * N_EDGES + 255) / 256, 256>>>(edges);
    k_wsum<<<(2 * C * C + 255) / 256, 256>>>(Wr, bl);
    k_wprep<<<dim3(16, 17), dim3(32, 8)>>>(Wp, Wl0, Wr0, Wl);

    // layer 0
    k_proj3<<<gMma, 256, SMEM_PROJ_BYTES>>>(x, bp, m0, m1, m2);
    k_agg3<<<gWarp, 256>>>(m0, m1, m2);
    k_dual0<<<gMma, 256, SMEM_DUAL_BYTES>>>(x, bl0, ln_g, ln_b);

    // layer 1: h = LN(relu((Σ agg@Wl + h@ΣWr + Σb)/3))
    k_agg3<<<gWarp, 256>>>(hf, hf, hf);
    k_mma<<<gMma, 256, SMEM_MMA_BYTES>>>(
        aggh, aggl, aggh + (size_t)NC, aggl + (size_t)NC,
        aggh + 2 * (size_t)NC, aggl + 2 * (size_t)NC, hh, hl,
        9, 10, 11, 15, bsum, ln_g + C, ln_b + C, hf, 3);

    // layer 2: out = (Σ agg@Wl + h@ΣWr + Σb)/3
    k_agg3<<<gWarp, 256>>>(hf, hf, hf);
    k_mma<<<gMma, 256, SMEM_MMA_BYTES>>>(
        aggh, aggl, aggh + (size_t)NC, aggl + (size_t)NC,
        aggh + 2 * (size_t)NC, aggl + 2 * (size_t)NC, hh, hl,
        12, 13, 14, 16, bsum + C, ln_g, ln_b, out, 2);
}

// round 8
// speedup vs baseline: 1.3204x; 1.3204x over previous
#include <cuda_runtime.h>
#include <cuda_bf16.h>
#include <cstdint>

#define N_NODES 100000
#define N_EDGES 500000
#define ET 3
#define C 128
#define LN_EPS 1e-5f
#define L2_EPS 1e-12f

#define PITCH 40                   // halves per smem row (bank-conflict-free)
#define CH (128 * PITCH)           // halves per 128x32 chunk plane

// ---------------- scratch (static device globals; no allocation) ----------------
__device__ float g_msg[N_NODES * C];    // msg0
__device__ float g_accb[N_NODES * C];   // msg1
__device__ float g_h[N_NODES * C];      // msg2, later h
__device__ float g_agg0[N_NODES * C];
__device__ float g_agg1[N_NODES * C];
__device__ float g_agg2[N_NODES * C];
__device__ __nv_bfloat16 g_wth[17 * C * C];   // transposed+split weights [n][k], hi
__device__ __nv_bfloat16 g_wtl[17 * C * C];   // lo
__device__ float g_wsum[2 * C * C];
__device__ float g_bsum[2 * C];
__device__ float g_invdeg[ET * N_NODES];
__device__ int g_cnt[ET * N_NODES];
__device__ int g_cur[ET * N_NODES];
__device__ int g_rowptr[ET * (N_NODES + 1)];
__device__ int g_col[ET * N_EDGES];
__device__ int g_bofs[ET * 128];

// ---------------- CSR build ----------------
__global__ void k_zero_int() {
    int i = blockIdx.x * blockDim.x + threadIdx.x;
    if (i < ET * N_NODES) { g_cnt[i] = 0; g_cur[i] = 0; }
}
__global__ void k_hist(const int* __restrict__ edges) {
    int i = blockIdx.x * blockDim.x + threadIdx.x;
    if (i >= ET * N_EDGES) return;
    int t = i / N_EDGES, e = i - t * N_EDGES;
    int dst = edges[(t * 2 + 1) * N_EDGES + e];
    atomicAdd(&g_cnt[t * N_NODES + dst], 1);
}
__global__ void k_scan1() {
    int t = blockIdx.y;
    int i = blockIdx.x * 1024 + threadIdx.x;
    __shared__ int sm[1024];
    int v = (i < N_NODES) ? g_cnt[t * N_NODES + i] : 0;
    sm[threadIdx.x] = v;
    __syncthreads();
    for (int off = 1; off < 1024; off <<= 1) {
        int add = (threadIdx.x >= off) ? sm[threadIdx.x - off] : 0;
        __syncthreads();
        sm[threadIdx.x] += add;
        __syncthreads();
    }
    if (i < N_NODES) g_rowptr[t * (N_NODES + 1) + i] = sm[threadIdx.x] - v;
    if (threadIdx.x == 1023) g_bofs[t * 128 + blockIdx.x] = sm[1023];
}
__global__ void k_scan2() {
    int t = threadIdx.x;
    if (t >= ET) return;
    int nb = (N_NODES + 1023) / 1024;
    int run = 0;
    for (int b = 0; b < nb; b++) { int v = g_bofs[t * 128 + b]; g_bofs[t * 128 + b] = run; run += v; }
    g_rowptr[t * (N_NODES + 1) + N_NODES] = run;
}
__global__ void k_scan3() {
    int t = blockIdx.y;
    int i = blockIdx.x * 1024 + threadIdx.x;
    if (i < N_NODES) g_rowptr[t * (N_NODES + 1) + i] += g_bofs[t * 128 + blockIdx.x];
}
__global__ void k_invdeg() {
    int i = blockIdx.x * blockDim.x + threadIdx.x;
    if (i < ET * N_NODES) {
        int c = g_cnt[i];
        g_invdeg[i] = 1.0f / (float)(c > 1 ? c : 1);
    }
}
__global__ void k_scatter(const int* __restrict__ edges) {
    int i = blockIdx.x * blockDim.x + threadIdx.x;
    if (i >= ET * N_EDGES) return;
    int t = i / N_EDGES, e = i - t * N_EDGES;
    int src = edges[t * 2 * N_EDGES + e];
    int dst = edges[(t * 2 + 1) * N_EDGES + e];
    int pos = g_rowptr[t * (N_NODES + 1) + dst] + atomicAdd(&g_cur[t * N_NODES + dst], 1);
    g_col[t * N_EDGES + pos] = src;
}

// ---------------- weight pre-sum ----------------
__global__ void k_wsum(const float* __restrict__ Wr, const float* __restrict__ bl) {
    int i = blockIdx.x * blockDim.x + threadIdx.x;
    if (i < 2 * C * C) {
        int l = i / (C * C), idx = i - l * (C * C);
        g_wsum[i] = Wr[(l * 3 + 0) * C * C + idx] + Wr[(l * 3 + 1) * C * C + idx]
                  + Wr[(l * 3 + 2) * C * C + idx];
    }
    if (i < 2 * C) {
        int l = i / C, cc = i - l * C;
        g_bsum[i] = bl[(l * 3 + 0) * C + cc] + bl[(l * 3 + 1) * C + cc] + bl[(l * 3 + 2) * C + cc];
    }
}

__device__ __forceinline__ void split2(float x, __nv_bfloat16& hi, __nv_bfloat16& lo) {
    hi = __float2bfloat16_rn(x);
    lo = __float2bfloat16_rn(x - __bfloat162float(hi));
}

// ---------------- transpose + split all 17 weight matrices into bf16 planes ----------------
// mats: 0-2 Wp, 3-5 Wl0, 6-8 Wr0, 9-14 Wl, 15-16 wsum.  out[m][n][k] = split(W[m][k][n])
__global__ void k_wprep(const float* __restrict__ Wp, const float* __restrict__ Wl0,
                        const float* __restrict__ Wr0, const float* __restrict__ Wl) {
    int m = blockIdx.y;
    const float* src;
    if (m < 3) src = Wp + (size_t)m * C * C;
    else if (m < 6) src = Wl0 + (size_t)(m - 3) * C * C;
    else if (m < 9) src = Wr0 + (size_t)(m - 6) * C * C;
    else if (m < 15) src = Wl + (size_t)(m - 9) * C * C;
    else src = g_wsum + (size_t)(m - 15) * C * C;
    __shared__ float tile[32][33];
    int txt = (blockIdx.x & 3) * 32, tyt = (blockIdx.x >> 2) * 32;
    int tx = threadIdx.x, ty = threadIdx.y;
    #pragma unroll
    for (int i = 0; i < 4; i++)
        tile[ty + i * 8][tx] = src[(size_t)(tyt + ty + i * 8) * C + txt + tx];
    __syncthreads();
    #pragma unroll
    for (int i = 0; i < 4; i++) {
        int n = txt + ty + i * 8, k = tyt + tx;
        float v = tile[tx][ty + i * 8];
        __nv_bfloat16 hi, lo; split2(v, hi, lo);
        g_wth[(size_t)m * C * C + n * C + k] = hi;
        g_wtl[(size_t)m * C * C + n * C + k] = lo;
    }
}

// ---------------- fused 3-type mean aggregation (warp per node) ----------------
__global__ void k_agg3(const float* __restrict__ f0, const float* __restrict__ f1,
                       const float* __restrict__ f2,
                       float* __restrict__ o0, float* __restrict__ o1, float* __restrict__ o2) {
    int w = (blockIdx.x * blockDim.x + threadIdx.x) >> 5;
    int lane = threadIdx.x & 31;
    if (w >= N_NODES) return;
    const float* feats[3] = {f0, f1, f2};
    float* outs[3] = {o0, o1, o2};
    #pragma unroll
    for (int t = 0; t < 3; t++) {
        const int* rp = &g_rowptr[t * (N_NODES + 1)];
        int s = rp[w], e = rp[w + 1];
        const int* col = &g_col[t * N_EDGES];
        const float* feat = feats[t];
        float4 acc = make_float4(0.f, 0.f, 0.f, 0.f);
        for (int j = s; j < e; j++) {
            int src = col[j];
            float4 v = *reinterpret_cast<const float4*>(&feat[(size_t)src * C + lane * 4]);
            acc.x += v.x; acc.y += v.y; acc.z += v.z; acc.w += v.w;
        }
        float inv = g_invdeg[t * N_NODES + w];
        acc.x *= inv; acc.y *= inv; acc.z *= inv; acc.w *= inv;
        *reinterpret_cast<float4*>(&outs[t][(size_t)w * C + lane * 4]) = acc;
    }
}

// ---------------- MMA primitives ----------------
__device__ __forceinline__ void mma_bf16(float* d, const uint32_t* a, uint32_t b0, uint32_t b1) {
    asm volatile(
        "mma.sync.aligned.m16n8k16.row.col.f32.bf16.bf16.f32 "
        "{%0,%1,%2,%3}, {%4,%5,%6,%7}, {%8,%9}, {%0,%1,%2,%3};"
        : "+f"(d[0]), "+f"(d[1]), "+f"(d[2]), "+f"(d[3])
        : "r"(a[0]), "r"(a[1]), "r"(a[2]), "r"(a[3]), "r"(b0), "r"(b1));
}
__device__ __forceinline__ void split_store4(__nv_bfloat16* hi, __nv_bfloat16* lo,
                                             int idx, float4 v) {
    __nv_bfloat16 hx, lx, hy, ly, hz, lz, hw, lw;
    split2(v.x, hx, lx); split2(v.y, hy, ly);
    split2(v.z, hz, lz); split2(v.w, hw, lw);
    __nv_bfloat162 h01; h01.x = hx; h01.y = hy;
    __nv_bfloat162 h23; h23.x = hz; h23.y = hw;
    __nv_bfloat162 l01; l01.x = lx; l01.y = ly;
    __nv_bfloat162 l23; l23.x = lz; l23.y = lw;
    *reinterpret_cast<__nv_bfloat162*>(&hi[idx]) = h01;
    *reinterpret_cast<__nv_bfloat162*>(&hi[idx + 2]) = h23;
    *reinterpret_cast<__nv_bfloat162*>(&lo[idx]) = l01;
    *reinterpret_cast<__nv_bfloat162*>(&lo[idx + 2]) = l23;
}
// load pre-split B chunk (mat, k-chunk kc) into smem planes; thread layout ar=t>>1, sel=t&1
__device__ __forceinline__ void load_B_planes(__nv_bfloat16* Bhi, __nv_bfloat16* Blo,
                                              int mat, int kc, int ar, int sel) {
    size_t be = (size_t)mat * C * C + (size_t)ar * C + kc + sel * 16;
    int idx = ar * PITCH + sel * 16;
    *reinterpret_cast<uint4*>(&Bhi[idx]) = *reinterpret_cast<const uint4*>(&g_wth[be]);
    *reinterpret_cast<uint4*>(&Bhi[idx + 8]) = *reinterpret_cast<const uint4*>(&g_wth[be + 8]);
    *reinterpret_cast<uint4*>(&Blo[idx]) = *reinterpret_cast<const uint4*>(&g_wtl[be]);
    *reinterpret_cast<uint4*>(&Blo[idx + 8]) = *reinterpret_cast<const uint4*>(&g_wtl[be + 8]);
}

// compute one 128x128x32 chunk stage (3-term split-bf16)
__device__ __forceinline__ void mma_stage(
    const __nv_bfloat16* __restrict__ Ahi, const __nv_bfloat16* __restrict__ Alo,
    const __nv_bfloat16* __restrict__ Bhi, const __nv_bfloat16* __restrict__ Blo,
    int wm, int wn, int g, int tg, float (*acc)[8][4])
{
    #pragma unroll
    for (int ks = 0; ks < 2; ks++) {
        int kk = ks * 16;
        uint32_t ah[2][4], al[2][4];
        #pragma unroll
        for (int mi = 0; mi < 2; mi++) {
            int m = wm * 32 + mi * 16 + g;
            int base = m * PITCH + kk + 2 * tg;
            ah[mi][0] = *reinterpret_cast<const uint32_t*>(&Ahi[base]);
            ah[mi][1] = *reinterpret_cast<const uint32_t*>(&Ahi[base + 8 * PITCH]);
            ah[mi][2] = *reinterpret_cast<const uint32_t*>(&Ahi[base + 8]);
            ah[mi][3] = *reinterpret_cast<const uint32_t*>(&Ahi[base + 8 * PITCH + 8]);
            al[mi][0] = *reinterpret_cast<const uint32_t*>(&Alo[base]);
            al[mi][1] = *reinterpret_cast<const uint32_t*>(&Alo[base + 8 * PITCH]);
            al[mi][2] = *reinterpret_cast<const uint32_t*>(&Alo[base + 8]);
            al[mi][3] = *reinterpret_cast<const uint32_t*>(&Alo[base + 8 * PITCH + 8]);
        }
        #pragma unroll
        for (int ni = 0; ni < 8; ni++) {
            int n = wn * 64 + ni * 8 + g;
            int bbase = n * PITCH + kk + 2 * tg;
            uint32_t bh0 = *reinterpret_cast<const uint32_t*>(&Bhi[bbase]);
            uint32_t bh1 = *reinterpret_cast<const uint32_t*>(&Bhi[bbase + 8]);
            uint32_t bl0 = *reinterpret_cast<const uint32_t*>(&Blo[bbase]);
            uint32_t bl1 = *reinterpret_cast<const uint32_t*>(&Blo[bbase + 8]);
            #pragma unroll
            for (int mi = 0; mi < 2; mi++) {
                mma_bf16(acc[mi][ni], ah[mi], bh0, bh1);
                mma_bf16(acc[mi][ni], ah[mi], bl0, bl1);
                mma_bf16(acc[mi][ni], al[mi], bh0, bh1);
            }
        }
    }
}

// ---------------- batched layer-0 projection: msg_t = relu(x@Wp_t + bp_t) ----------------
#define SMEM_PROJ_BYTES (10 * CH * 2)      // 102400
__global__ __launch_bounds__(256) void k_proj3(
    const float* __restrict__ x, const float* __restrict__ bp,
    float* __restrict__ m0, float* __restrict__ m1, float* __restrict__ m2)
{
    extern __shared__ char smem[];
    __nv_bfloat16* Ahi = (__nv_bfloat16*)smem;      // 4 chunks resident
    __nv_bfloat16* Alo = Ahi + 4 * CH;
    __nv_bfloat16* Bhi = Alo + 4 * CH;
    __nv_bfloat16* Blo = Bhi + CH;

    int t = threadIdx.x, lane = t & 31, wid = t >> 5;
    int g = lane >> 2, tg = lane & 3;
    int wm = wid & 3, wn = wid >> 2;
    int row0 = blockIdx.x * 128;
    int ar = t >> 1, sel = t & 1;
    int kq = sel * 16;
    int gr = row0 + ar;
    bool valid = gr < N_NODES;

    // load full x tile (128x128) once
    #pragma unroll
    for (int c = 0; c < 4; c++)
        #pragma unroll
        for (int q = 0; q < 4; q++) {
            float4 v = valid ? *reinterpret_cast<const float4*>(&x[(size_t)gr * C + c * 32 + kq + q * 4])
                             : make_float4(0.f, 0.f, 0.f, 0.f);
            split_store4(Ahi, Alo, c * CH + ar * PITCH + kq + q * 4, v);
        }
    __syncthreads();

    float* msgs[3] = {m0, m1, m2};
    for (int tt = 0; tt < 3; tt++) {
        float acc[2][8][4];
        #pragma unroll
        for (int mi = 0; mi < 2; mi++)
            #pragma unroll
            for (int ni = 0; ni < 8; ni++)
                #pragma unroll
                for (int r = 0; r < 4; r++) acc[mi][ni][r] = 0.f;

        for (int s = 0; s < 4; s++) {
            load_B_planes(Bhi, Blo, tt, s * 32, ar, sel);
            __syncthreads();
            mma_stage(Ahi + s * CH, Alo + s * CH, Bhi, Blo, wm, wn, g, tg, acc);
            __syncthreads();
        }
        // epilogue: bias + relu -> msg_tt
        const float* bias = bp + tt * C;
        float* out = msgs[tt];
        #pragma unroll
        for (int mi = 0; mi < 2; mi++) {
            int r0 = row0 + wm * 32 + mi * 16 + g, r1 = r0 + 8;
            #pragma unroll
            for (int ni = 0; ni < 8; ni++) {
                int coln = wn * 64 + ni * 8 + tg * 2;
                float2 bv = *reinterpret_cast<const float2*>(&bias[coln]);
                float2 o0, o1;
                o0.x = fmaxf(acc[mi][ni][0] + bv.x, 0.f);
                o0.y = fmaxf(acc[mi][ni][1] + bv.y, 0.f);
                o1.x = fmaxf(acc[mi][ni][2] + bv.x, 0.f);
                o1.y = fmaxf(acc[mi][ni][3] + bv.y, 0.f);
                if (r0 < N_NODES) *reinterpret_cast<float2*>(&out[(size_t)r0 * C + coln]) = o0;
                if (r1 < N_NODES) *reinterpret_cast<float2*>(&out[(size_t)r1 * C + coln]) = o1;
            }
        }
    }
}

// ---------------- batched layer-0 dual GEMM + norm-accumulate + relu/3 + LN -> h ----------------
#define ACCP 132
#define SMEM_DUAL_BYTES (12 * CH * 2 + 128 * ACCP * 4 + 256 * 4 + 128 * 4)   // 192000
__global__ __launch_bounds__(256) void k_dual0(
    const float* __restrict__ x,
    const float* __restrict__ a0, const float* __restrict__ a1, const float* __restrict__ a2,
    const float* __restrict__ bl0,
    const float* __restrict__ lng, const float* __restrict__ lnb,
    float* __restrict__ hout)
{
    extern __shared__ char smem[];
    __nv_bfloat16* xAhi = (__nv_bfloat16*)smem;     // 4 chunks resident
    __nv_bfloat16* xAlo = xAhi + 4 * CH;
    __nv_bfloat16* gAhi = xAlo + 4 * CH;            // agg chunk (1)
    __nv_bfloat16* gAlo = gAhi + CH;
    __nv_bfloat16* Bhi  = gAlo + CH;
    __nv_bfloat16* Blo  = Bhi + CH;
    float* accum = (float*)(smem + 12 * CH * 2);    // [128][ACCP]
    float* red   = accum + 128 * ACCP;              // [128][2]
    float* invn  = red + 256;                       // [128]

    int t = threadIdx.x, lane = t & 31, wid = t >> 5;
    int g = lane >> 2, tg = lane & 3;
    int wm = wid & 3, wn = wid >> 2;
    int row0 = blockIdx.x * 128;
    int ar = t >> 1, sel = t & 1;
    int kq = sel * 16;
    int gr = row0 + ar;
    bool valid = gr < N_NODES;

    // resident x tile
    #pragma unroll
    for (int c = 0; c < 4; c++)
        #pragma unroll
        for (int q = 0; q < 4; q++) {
            float4 v = valid ? *reinterpret_cast<const float4*>(&x[(size_t)gr * C + c * 32 + kq + q * 4])
                             : make_float4(0.f, 0.f, 0.f, 0.f);
            split_store4(xAhi, xAlo, c * CH + ar * PITCH + kq + q * 4, v);
        }
    // zero accum
    for (int i = t; i < 128 * ACCP; i += 256) accum[i] = 0.f;
    __syncthreads();

    const float* aggs[3] = {a0, a1, a2};
    for (int tt = 0; tt < 3; tt++) {
        float acc[2][8][4];
        #pragma unroll
        for (int mi = 0; mi < 2; mi++)
            #pragma unroll
            for (int ni = 0; ni < 8; ni++)
                #pragma unroll
                for (int r = 0; r < 4; r++) acc[mi][ni][r] = 0.f;

        const float* Ag = aggs[tt];

        // pass 1: agg_t @ Wl0_t   (mat 3+tt)
        for (int s = 0; s < 4; s++) {
            int kc = s * 32;
            #pragma unroll
            for (int q = 0; q < 4; q++) {
                float4 v = valid ? *reinterpret_cast<const float4*>(&Ag[(size_t)gr * C + kc + kq + q * 4])
                                 : make_float4(0.f, 0.f, 0.f, 0.f);
                split_store4(gAhi, gAlo, ar * PITCH + kq + q * 4, v);
            }
            load_B_planes(Bhi, Blo, 3 + tt, kc, ar, sel);
            __syncthreads();
            mma_stage(gAhi, gAlo, Bhi, Blo, wm, wn, g, tg, acc);
            __syncthreads();
        }
        // pass 2: x @ Wr0_t (x resident, mat 6+tt)
        for (int s = 0; s < 4; s++) {
            load_B_planes(Bhi, Blo, 6 + tt, s * 32, ar, sel);
            __syncthreads();
            mma_stage(xAhi + s * CH, xAlo + s * CH, Bhi, Blo, wm, wn, g, tg, acc);
            __syncthreads();
        }
        // bias
        const float* bias = bl0 + tt * C;
        #pragma unroll
        for (int ni = 0; ni < 8; ni++) {
            int coln = wn * 64 + ni * 8 + tg * 2;
            float2 bv = *reinterpret_cast<const float2*>(&bias[coln]);
            #pragma unroll
            for (int mi = 0; mi < 2; mi++) {
                acc[mi][ni][0] += bv.x; acc[mi][ni][1] += bv.y;
                acc[mi][ni][2] += bv.x; acc[mi][ni][3] += bv.y;
            }
        }
        // per-row L2 norm
        float ss0[2] = {0.f, 0.f}, ss1[2] = {0.f, 0.f};
        #pragma unroll
        for (int mi = 0; mi < 2; mi++)
            #pragma unroll
            for (int ni = 0; ni < 8; ni++) {
                ss0[mi] += acc[mi][ni][0] * acc[mi][ni][0] + acc[mi][ni][1] * acc[mi][ni][1];
                ss1[mi] += acc[mi][ni][2] * acc[mi][ni][2] + acc[mi][ni][3] * acc[mi][ni][3];
            }
        #pragma unroll
        for (int mi = 0; mi < 2; mi++) {
            ss0[mi] += __shfl_xor_sync(0xffffffffu, ss0[mi], 1);
            ss0[mi] += __shfl_xor_sync(0xffffffffu, ss0[mi], 2);
            ss1[mi] += __shfl_xor_sync(0xffffffffu, ss1[mi], 1);
            ss1[mi] += __shfl_xor_sync(0xffffffffu, ss1[mi], 2);
        }
        if (tg == 0) {
            #pragma unroll
            for (int mi = 0; mi < 2; mi++) {
                red[(wm * 32 + mi * 16 + g) * 2 + wn] = ss0[mi];
                red[(wm * 32 + mi * 16 + 8 + g) * 2 + wn] = ss1[mi];
            }
        }
        __syncthreads();
        if (t < 128) invn[t] = 1.f / fmaxf(sqrtf(red[t * 2] + red[t * 2 + 1]), L2_EPS);
        __syncthreads();
        // accumulate normalized values into smem accum
        #pragma unroll
        for (int mi = 0; mi < 2; mi++) {
            int lr0 = wm * 32 + mi * 16 + g;
            float i0 = invn[lr0], i1 = invn[lr0 + 8];
            #pragma unroll
            for (int ni = 0; ni < 8; ni++) {
                int coln = wn * 64 + ni * 8 + tg * 2;
                accum[lr0 * ACCP + coln]       += acc[mi][ni][0] * i0;
                accum[lr0 * ACCP + coln + 1]   += acc[mi][ni][1] * i0;
                accum[(lr0 + 8) * ACCP + coln]     += acc[mi][ni][2] * i1;
                accum[(lr0 + 8) * ACCP + coln + 1] += acc[mi][ni][3] * i1;
            }
        }
        __syncthreads();
    }

    // final: h = LN(relu(accum/3))
    {
        int row = t >> 1, halfc = t & 1;
        int c0 = halfc * 64;
        float s = 0.f, q = 0.f;
        #pragma unroll
        for (int i = 0; i < 16; i++) {
            float4 v = *reinterpret_cast<float4*>(&accum[row * ACCP + c0 + i * 4]);
            v.x = fmaxf(v.x * (1.f / 3.f), 0.f);
            v.y = fmaxf(v.y * (1.f / 3.f), 0.f);
            v.z = fmaxf(v.z * (1.f / 3.f), 0.f);
            v.w = fmaxf(v.w * (1.f / 3.f), 0.f);
            s += v.x + v.y + v.z + v.w;
            q += v.x * v.x + v.y * v.y + v.z * v.z + v.w * v.w;
        }
        s += __shfl_xor_sync(0xffffffffu, s, 1);
        q += __shfl_xor_sync(0xffffffffu, q, 1);
        float mean = s * (1.f / 128.f);
        float var = q * (1.f / 128.f) - mean * mean;
        float rstd = rsqrtf(fmaxf(var, 0.f) + LN_EPS);
        int grow = row0 + row;
        if (grow < N_NODES) {
            #pragma unroll
            for (int i = 0; i < 16; i++) {
                float4 v = *reinterpret_cast<float4*>(&accum[row * ACCP + c0 + i * 4]);
                float4 gg = *reinterpret_cast<const float4*>(&lng[c0 + i * 4]);
                float4 bb = *reinterpret_cast<const float4*>(&lnb[c0 + i * 4]);
                float4 o;
                o.x = (fmaxf(v.x * (1.f / 3.f), 0.f) - mean) * rstd * gg.x + bb.x;
                o.y = (fmaxf(v.y * (1.f / 3.f), 0.f) - mean) * rstd * gg.y + bb.y;
                o.z = (fmaxf(v.z * (1.f / 3.f), 0.f) - mean) * rstd * gg.z + bb.z;
                o.w = (fmaxf(v.w * (1.f / 3.f), 0.f) - mean) * rstd * gg.w + bb.w;
                *reinterpret_cast<float4*>(&hout[(size_t)grow * C + c0 + i * 4]) = o;
            }
        }
    }
}

// ---------------- generic K=512 GEMM (layers 1..2) ----------------
// mode 2: out = (acc+bias)/3
// mode 3: out = LN(relu((acc+bias)/3))
#define SMEM_MMA_BYTES (4 * CH * 2)    // 40960
__global__ __launch_bounds__(256, 2) void k_mma(
    const float* __restrict__ A0, const float* __restrict__ A1,
    const float* __restrict__ A2, const float* __restrict__ A3,
    int m0, int m1, int m2, int m3,
    const float* __restrict__ bias, const float* __restrict__ lng,
    const float* __restrict__ lnb, float* __restrict__ out, int mode)
{
    extern __shared__ char smem[];
    __nv_bfloat16* Ahi = (__nv_bfloat16*)smem;
    __nv_bfloat16* Alo = Ahi + CH;
    __nv_bfloat16* Bhi = Alo + CH;
    __nv_bfloat16* Blo = Bhi + CH;

    int t = threadIdx.x, lane = t & 31, wid = t >> 5;
    int g = lane >> 2, tg = lane & 3;
    int wm = wid & 3, wn = wid >> 2;
    int row0 = blockIdx.x * 128;
    int ar = t >> 1, sel = t & 1;
    int kq = sel * 16;
    int gr = row0 + ar;
    bool valid = gr < N_NODES;

    const float* Aarr[4] = {A0, A1, A2, A3};
    int mats[4] = {m0, m1, m2, m3};

    float acc[2][8][4];
    #pragma unroll
    for (int mi = 0; mi < 2; mi++)
        #pragma unroll
        for (int ni = 0; ni < 8; ni++)
            #pragma unroll
            for (int r = 0; r < 4; r++) acc[mi][ni][r] = 0.f;

    for (int s = 0; s < 16; s++) {
        const float* Ac = Aarr[s >> 2];
        int kc = (s & 3) * 32;
        #pragma unroll
        for (int q = 0; q < 4; q++) {
            float4 v = valid ? *reinterpret_cast<const float4*>(&Ac[(size_t)gr * C + kc + kq + q * 4])
                             : make_float4(0.f, 0.f, 0.f, 0.f);
            split_store4(Ahi, Alo, ar * PITCH + kq + q * 4, v);
        }
        load_B_planes(Bhi, Blo, mats[s >> 2], kc, ar, sel);
        __syncthreads();
        mma_stage(Ahi, Alo, Bhi, Blo, wm, wn, g, tg, acc);
        __syncthreads();
    }

    // bias + scale (+relu for mode 3)
    const float sc = 1.f / 3.f;
    #pragma unroll
    for (int ni = 0; ni < 8; ni++) {
        int coln = wn * 64 + ni * 8 + tg * 2;
        float2 bv = *reinterpret_cast<const float2*>(&bias[coln]);
        #pragma unroll
        for (int mi = 0; mi < 2; mi++) {
            acc[mi][ni][0] = (acc[mi][ni][0] + bv.x) * sc;
            acc[mi][ni][1] = (acc[mi][ni][1] + bv.y) * sc;
            acc[mi][ni][2] = (acc[mi][ni][2] + bv.x) * sc;
            acc[mi][ni][3] = (acc[mi][ni][3] + bv.y) * sc;
            if (mode == 3) {
                acc[mi][ni][0] = fmaxf(acc[mi][ni][0], 0.f);
                acc[mi][ni][1] = fmaxf(acc[mi][ni][1], 0.f);
                acc[mi][ni][2] = fmaxf(acc[mi][ni][2], 0.f);
                acc[mi][ni][3] = fmaxf(acc[mi][ni][3], 0.f);
            }
        }
    }

    if (mode == 3) {
        float* red_s = (float*)smem;     // [128][2]
        float* red_q = red_s + 256;      // [128][2]
        float* rmean = red_q + 256;      // [128]
        float* rstdv = rmean + 128;      // [128]
        float s0[2] = {0.f, 0.f}, q0[2] = {0.f, 0.f};
        float s1[2] = {0.f, 0.f}, q1[2] = {0.f, 0.f};
        #pragma unroll
        for (int mi = 0; mi < 2; mi++)
            #pragma unroll
            for (int ni = 0; ni < 8; ni++) {
                s0[mi] += acc[mi][ni][0] + acc[mi][ni][1];
                q0[mi] += acc[mi][ni][0] * acc[mi][ni][0] + acc[mi][ni][1] * acc[mi][ni][1];
                s1[mi] += acc[mi][ni][2] + acc[mi][ni][3];
                q1[mi] += acc[mi][ni][2] * acc[mi][ni][2] + acc[mi][ni][3] * acc[mi][ni][3];
            }
        #pragma unroll
        for (int mi = 0; mi < 2; mi++) {
            s0[mi] += __shfl_xor_sync(0xffffffffu, s0[mi], 1);
            s0[mi] += __shfl_xor_sync(0xffffffffu, s0[mi], 2);
            q0[mi] += __shfl_xor_sync(0xffffffffu, q0[mi], 1);
            q0[mi] += __shfl_xor_sync(0xffffffffu, q0[mi], 2);
            s1[mi] += __shfl_xor_sync(0xffffffffu, s1[mi], 1);
            s1[mi] += __shfl_xor_sync(0xffffffffu, s1[mi], 2);
            q1[mi] += __shfl_xor_sync(0xffffffffu, q1[mi], 1);
            q1[mi] += __shfl_xor_sync(0xffffffffu, q1[mi], 2);
        }
        if (tg == 0) {
            #pragma unroll
            for (int mi = 0; mi < 2; mi++) {
                int lr = wm * 32 + mi * 16 + g;
                red_s[lr * 2 + wn] = s0[mi];
                red_q[lr * 2 + wn] = q0[mi];
                red_s[(lr + 8) * 2 + wn] = s1[mi];
                red_q[(lr + 8) * 2 + wn] = q1[mi];
            }
        }
        __syncthreads();
        if (t < 128) {
            float ssum = red_s[t * 2] + red_s[t * 2 + 1];
            float qsum = red_q[t * 2] + red_q[t * 2 + 1];
            float mean = ssum * (1.f / 128.f);
            float var = qsum * (1.f / 128.f) - mean * mean;
            rmean[t] = mean;
            rstdv[t] = rsqrtf(fmaxf(var, 0.f) + LN_EPS);
        }
        __syncthreads();
        #pragma unroll
        for (int mi = 0; mi < 2; mi++) {
            int lr0 = wm * 32 + mi * 16 + g;
            int r0 = row0 + lr0, r1 = r0 + 8;
            float m0v = rmean[lr0], d0 = rstdv[lr0];
            float m1v = rmean[lr0 + 8], d1 = rstdv[lr0 + 8];
            #pragma unroll
            for (int ni = 0; ni < 8; ni++) {
                int coln = wn * 64 + ni * 8 + tg * 2;
                float2 gv = *reinterpret_cast<const float2*>(&lng[coln]);
                float2 bb = *reinterpret_cast<const float2*>(&lnb[coln]);
                if (r0 < N_NODES) {
                    float2 o;
                    o.x = (acc[mi][ni][0] - m0v) * d0 * gv.x + bb.x;
                    o.y = (acc[mi][ni][1] - m0v) * d0 * gv.y + bb.y;
                    *reinterpret_cast<float2*>(&out[(size_t)r0 * C + coln]) = o;
                }
                if (r1 < N_NODES) {
                    float2 o;
                    o.x = (acc[mi][ni][2] - m1v) * d1 * gv.x + bb.x;
                    o.y = (acc[mi][ni][3] - m1v) * d1 * gv.y + bb.y;
                    *reinterpret_cast<float2*>(&out[(size_t)r1 * C + coln]) = o;
                }
            }
        }
    } else {
        #pragma unroll
        for (int mi = 0; mi < 2; mi++) {
            int r0 = row0 + wm * 32 + mi * 16 + g, r1 = r0 + 8;
            #pragma unroll
            for (int ni = 0; ni < 8; ni++) {
                int coln = wn * 64 + ni * 8 + tg * 2;
                if (r0 < N_NODES) {
                    float2 o; o.x = acc[mi][ni][0]; o.y = acc[mi][ni][1];
                    *reinterpret_cast<float2*>(&out[(size_t)r0 * C + coln]) = o;
                }
                if (r1 < N_NODES) {
                    float2 o; o.x = acc[mi][ni][2]; o.y = acc[mi][ni][3];
                    *reinterpret_cast<float2*>(&out[(size_t)r1 * C + coln]) = o;
                }
            }
        }
    }
}

// ---------------- host orchestration ----------------
extern "C" void kernel_launch(void* const* d_in, const int* in_sizes, int n_in,
                              void* d_out, int out_size) {
    const float* x    = (const float*)d_in[0];
    const int*   edges = (const int*)d_in[1];
    const float* Wp   = (const float*)d_in[2];
    const float* bp   = (const float*)d_in[3];
    const float* Wl0  = (const float*)d_in[4];
    const float* bl0  = (const float*)d_in[5];
    const float* Wr0  = (const float*)d_in[6];
    const float* Wl   = (const float*)d_in[7];
    const float* bl   = (const float*)d_in[8];
    const float* Wr   = (const float*)d_in[9];
    const float* ln_g = (const float*)d_in[10];
    const float* ln_b = (const float*)d_in[11];
    float* out = (float*)d_out;

    void* p;
    float *msg0, *msg1, *msg2, *h, *agg0, *agg1, *agg2, *bsum;
    cudaGetSymbolAddress(&p, g_msg);  msg0 = (float*)p;
    cudaGetSymbolAddress(&p, g_accb); msg1 = (float*)p;
    cudaGetSymbolAddress(&p, g_h);    msg2 = (float*)p;  h = (float*)p;
    cudaGetSymbolAddress(&p, g_agg0); agg0 = (float*)p;
    cudaGetSymbolAddress(&p, g_agg1); agg1 = (float*)p;
    cudaGetSymbolAddress(&p, g_agg2); agg2 = (float*)p;
    cudaGetSymbolAddress(&p, g_bsum); bsum = (float*)p;

    cudaFuncSetAttribute(k_proj3, cudaFuncAttributeMaxDynamicSharedMemorySize, SMEM_PROJ_BYTES);
    cudaFuncSetAttribute(k_dual0, cudaFuncAttributeMaxDynamicSharedMemorySize, SMEM_DUAL_BYTES);
    cudaFuncSetAttribute(k_mma, cudaFuncAttributeMaxDynamicSharedMemorySize, SMEM_MMA_BYTES);

    int nbScan = (N_NODES + 1023) / 1024;
    dim3 gScan(nbScan, ET);
    int gMma = (N_NODES + 127) / 128;
    int gWarp = (N_NODES * 32 + 255) / 256;

    // launches 1-3: weight prep (independent of CSR)
    k_wsum<<<(2 * C * C + 255) / 256, 256>>>(Wr, bl);
    k_wprep<<<dim3(16, 17), dim3(32, 8)>>>(Wp, Wl0, Wr0, Wl);
    k_zero_int<<<(ET * N_NODES + 255) / 256, 256>>>();

    // launch 4 (ncu capture slot): the batched projection GEMM
    k_proj3<<<gMma, 256, SMEM_PROJ_BYTES>>>(x, bp, msg0, msg1, msg2);

    // CSR build
    k_hist<<<(ET * N_EDGES + 255) / 256, 256>>>(edges);
    k_scan1<<<gScan, 1024>>>();
    k_scan2<<<1, 32>>>();
    k_scan3<<<gScan, 1024>>>();
    k_invdeg<<<(ET * N_NODES + 255) / 256, 256>>>();
    k_scatter<<<(ET * N_EDGES + 255) / 256, 256>>>(edges);

    // layer 0 aggregation + dual GEMM (+ fused relu/3 + LN) -> h
    k_agg3<<<gWarp, 256>>>(msg0, msg1, msg2, agg0, agg1, agg2);
    k_dual0<<<gMma, 256, SMEM_DUAL_BYTES>>>(x, agg0, agg1, agg2, bl0, ln_g, ln_b, h);

    // layer 1: h = LN(relu((Σ agg@Wl + h@ΣWr + Σb)/3))
    k_agg3<<<gWarp, 256>>>(h, h, h, agg0, agg1, agg2);
    k_mma<<<gMma, 256, SMEM_MMA_BYTES>>>(agg0, agg1, agg2, h,
                           9, 10, 11, 15, bsum, ln_g + C, ln_b + C, h, 3);

    // layer 2: out = (Σ agg@Wl + h@ΣWr + Σb)/3
    k_agg3<<<gWarp, 256>>>(h, h, h, agg0, agg1, agg2);
    k_mma<<<gMma, 256, SMEM_MMA_BYTES>>>(agg0, agg1, agg2, h,
                           12, 13, 14, 16, bsum + C, ln_g, ln_b, out, 2);
}

// round 9
// speedup vs baseline: 1.3750x; 1.0413x over previous
#include <cuda_runtime.h>
#include <cuda_bf16.h>
#include <cstdint>

#define N_NODES 100000
#define N_EDGES 500000
#define ET 3
#define C 128
#define LN_EPS 1e-5f
#define L2_EPS 1e-12f

#define PITCH 40                   // halves per smem row (bank-conflict-free)
#define CH (128 * PITCH)           // halves per 128x32 chunk plane
#define CB (CH * 2)                // bytes per plane (10240)

// ---------------- scratch (static device globals; no allocation) ----------------
__device__ float g_msg[N_NODES * C];    // msg0
__device__ float g_accb[N_NODES * C];   // msg1
__device__ float g_h[N_NODES * C];      // msg2, later h
__device__ float g_agg0[N_NODES * C];
__device__ float g_agg1[N_NODES * C];
__device__ float g_agg2[N_NODES * C];
__device__ __nv_bfloat16 g_wth[17 * C * C];   // transposed+split weights [n][k], hi
__device__ __nv_bfloat16 g_wtl[17 * C * C];   // lo
__device__ float g_wsum[2 * C * C];
__device__ float g_bsum[2 * C];
__device__ float g_invdeg[ET * N_NODES];
__device__ int g_cnt[ET * N_NODES];
__device__ int g_cur[ET * N_NODES];
__device__ int g_rowptr[ET * (N_NODES + 1)];
__device__ int g_col[ET * N_EDGES];
__device__ int g_bofs[ET * 128];

// ---------------- CSR build ----------------
__global__ void k_zero_int() {
    int i = blockIdx.x * blockDim.x + threadIdx.x;
    if (i < ET * N_NODES) { g_cnt[i] = 0; g_cur[i] = 0; }
}
__global__ void k_hist(const int* __restrict__ edges) {
    int i = blockIdx.x * blockDim.x + threadIdx.x;
    if (i >= ET * N_EDGES) return;
    int t = i / N_EDGES, e = i - t * N_EDGES;
    int dst = edges[(t * 2 + 1) * N_EDGES + e];
    atomicAdd(&g_cnt[t * N_NODES + dst], 1);
}
__global__ void k_scan1() {
    int t = blockIdx.y;
    int i = blockIdx.x * 1024 + threadIdx.x;
    __shared__ int sm[1024];
    int v = (i < N_NODES) ? g_cnt[t * N_NODES + i] : 0;
    sm[threadIdx.x] = v;
    __syncthreads();
    for (int off = 1; off < 1024; off <<= 1) {
        int add = (threadIdx.x >= off) ? sm[threadIdx.x - off] : 0;
        __syncthreads();
        sm[threadIdx.x] += add;
        __syncthreads();
    }
    if (i < N_NODES) g_rowptr[t * (N_NODES + 1) + i] = sm[threadIdx.x] - v;
    if (threadIdx.x == 1023) g_bofs[t * 128 + blockIdx.x] = sm[1023];
}
__global__ void k_scan2() {
    int t = threadIdx.x;
    if (t >= ET) return;
    int nb = (N_NODES + 1023) / 1024;
    int run = 0;
    for (int b = 0; b < nb; b++) { int v = g_bofs[t * 128 + b]; g_bofs[t * 128 + b] = run; run += v; }
    g_rowptr[t * (N_NODES + 1) + N_NODES] = run;
}
__global__ void k_scan3() {
    int t = blockIdx.y;
    int i = blockIdx.x * 1024 + threadIdx.x;
    if (i < N_NODES) g_rowptr[t * (N_NODES + 1) + i] += g_bofs[t * 128 + blockIdx.x];
}
__global__ void k_invdeg() {
    int i = blockIdx.x * blockDim.x + threadIdx.x;
    if (i < ET * N_NODES) {
        int c = g_cnt[i];
        g_invdeg[i] = 1.0f / (float)(c > 1 ? c : 1);
    }
}
__global__ void k_scatter(const int* __restrict__ edges) {
    int i = blockIdx.x * blockDim.x + threadIdx.x;
    if (i >= ET * N_EDGES) return;
    int t = i / N_EDGES, e = i - t * N_EDGES;
    int src = edges[t * 2 * N_EDGES + e];
    int dst = edges[(t * 2 + 1) * N_EDGES + e];
    int pos = g_rowptr[t * (N_NODES + 1) + dst] + atomicAdd(&g_cur[t * N_NODES + dst], 1);
    g_col[t * N_EDGES + pos] = src;
}

// ---------------- weight pre-sum ----------------
__global__ void k_wsum(const float* __restrict__ Wr, const float* __restrict__ bl) {
    int i = blockIdx.x * blockDim.x + threadIdx.x;
    if (i < 2 * C * C) {
        int l = i / (C * C), idx = i - l * (C * C);
        g_wsum[i] = Wr[(l * 3 + 0) * C * C + idx] + Wr[(l * 3 + 1) * C * C + idx]
                  + Wr[(l * 3 + 2) * C * C + idx];
    }
    if (i < 2 * C) {
        int l = i / C, cc = i - l * C;
        g_bsum[i] = bl[(l * 3 + 0) * C + cc] + bl[(l * 3 + 1) * C + cc] + bl[(l * 3 + 2) * C + cc];
    }
}

__device__ __forceinline__ void split2(float x, __nv_bfloat16& hi, __nv_bfloat16& lo) {
    hi = __float2bfloat16_rn(x);
    lo = __float2bfloat16_rn(x - __bfloat162float(hi));
}
__device__ __forceinline__ uint32_t smem_u32(const void* p) {
    uint32_t a;
    asm("{ .reg .u64 t; cvta.to.shared.u64 t, %1; cvt.u32.u64 %0, t; }" : "=r"(a) : "l"(p));
    return a;
}

// ---------------- transpose + split all 17 weight matrices into bf16 planes ----------------
// mats: 0-2 Wp, 3-5 Wl0, 6-8 Wr0, 9-14 Wl, 15-16 wsum.  out[m][n][k] = split(W[m][k][n])
__global__ void k_wprep(const float* __restrict__ Wp, const float* __restrict__ Wl0,
                        const float* __restrict__ Wr0, const float* __restrict__ Wl) {
    int m = blockIdx.y;
    const float* src;
    if (m < 3) src = Wp + (size_t)m * C * C;
    else if (m < 6) src = Wl0 + (size_t)(m - 3) * C * C;
    else if (m < 9) src = Wr0 + (size_t)(m - 6) * C * C;
    else if (m < 15) src = Wl + (size_t)(m - 9) * C * C;
    else src = g_wsum + (size_t)(m - 15) * C * C;
    __shared__ float tile[32][33];
    int txt = (blockIdx.x & 3) * 32, tyt = (blockIdx.x >> 2) * 32;
    int tx = threadIdx.x, ty = threadIdx.y;
    #pragma unroll
    for (int i = 0; i < 4; i++)
        tile[ty + i * 8][tx] = src[(size_t)(tyt + ty + i * 8) * C + txt + tx];
    __syncthreads();
    #pragma unroll
    for (int i = 0; i < 4; i++) {
        int n = txt + ty + i * 8, k = tyt + tx;
        float v = tile[tx][ty + i * 8];
        __nv_bfloat16 hi, lo; split2(v, hi, lo);
        g_wth[(size_t)m * C * C + n * C + k] = hi;
        g_wtl[(size_t)m * C * C + n * C + k] = lo;
    }
}

// ---------------- fused 3-type mean aggregation (warp per node) ----------------
__global__ void k_agg3(const float* __restrict__ f0, const float* __restrict__ f1,
                       const float* __restrict__ f2,
                       float* __restrict__ o0, float* __restrict__ o1, float* __restrict__ o2) {
    int w = (blockIdx.x * blockDim.x + threadIdx.x) >> 5;
    int lane = threadIdx.x & 31;
    if (w >= N_NODES) return;
    const float* feats[3] = {f0, f1, f2};
    float* outs[3] = {o0, o1, o2};
    #pragma unroll
    for (int t = 0; t < 3; t++) {
        const int* rp = &g_rowptr[t * (N_NODES + 1)];
        int s = rp[w], e = rp[w + 1];
        const int* col = &g_col[t * N_EDGES];
        const float* feat = feats[t];
        float4 acc = make_float4(0.f, 0.f, 0.f, 0.f);
        for (int j = s; j < e; j++) {
            int src = col[j];
            float4 v = *reinterpret_cast<const float4*>(&feat[(size_t)src * C + lane * 4]);
            acc.x += v.x; acc.y += v.y; acc.z += v.z; acc.w += v.w;
        }
        float inv = g_invdeg[t * N_NODES + w];
        acc.x *= inv; acc.y *= inv; acc.z *= inv; acc.w *= inv;
        *reinterpret_cast<float4*>(&outs[t][(size_t)w * C + lane * 4]) = acc;
    }
}

// ---------------- MMA primitives ----------------
__device__ __forceinline__ void mma_bf16(float* d, const uint32_t* a, uint32_t b0, uint32_t b1) {
    asm volatile(
        "mma.sync.aligned.m16n8k16.row.col.f32.bf16.bf16.f32 "
        "{%0,%1,%2,%3}, {%4,%5,%6,%7}, {%8,%9}, {%0,%1,%2,%3};"
        : "+f"(d[0]), "+f"(d[1]), "+f"(d[2]), "+f"(d[3])
        : "r"(a[0]), "r"(a[1]), "r"(a[2]), "r"(a[3]), "r"(b0), "r"(b1));
}
__device__ __forceinline__ void ldsm4(uint32_t a, uint32_t& r0, uint32_t& r1,
                                      uint32_t& r2, uint32_t& r3) {
    asm volatile("ldmatrix.sync.aligned.m8n8.x4.shared.b16 {%0,%1,%2,%3}, [%4];"
                 : "=r"(r0), "=r"(r1), "=r"(r2), "=r"(r3) : "r"(a));
}
__device__ __forceinline__ void split_store4(__nv_bfloat16* hi, __nv_bfloat16* lo,
                                             int idx, float4 v) {
    __nv_bfloat16 hx, lx, hy, ly, hz, lz, hw, lw;
    split2(v.x, hx, lx); split2(v.y, hy, ly);
    split2(v.z, hz, lz); split2(v.w, hw, lw);
    __nv_bfloat162 h01; h01.x = hx; h01.y = hy;
    __nv_bfloat162 h23; h23.x = hz; h23.y = hw;
    __nv_bfloat162 l01; l01.x = lx; l01.y = ly;
    __nv_bfloat162 l23; l23.x = lz; l23.y = lw;
    *reinterpret_cast<__nv_bfloat162*>(&hi[idx]) = h01;
    *reinterpret_cast<__nv_bfloat162*>(&hi[idx + 2]) = h23;
    *reinterpret_cast<__nv_bfloat162*>(&lo[idx]) = l01;
    *reinterpret_cast<__nv_bfloat162*>(&lo[idx + 2]) = l23;
}
// load pre-split B chunk (mat, k-chunk kc) into smem planes; thread layout ar=t>>1, sel=t&1
__device__ __forceinline__ void load_B_planes(__nv_bfloat16* Bhi, __nv_bfloat16* Blo,
                                              int mat, int kc, int ar, int sel) {
    size_t be = (size_t)mat * C * C + (size_t)ar * C + kc + sel * 16;
    int idx = ar * PITCH + sel * 16;
    *reinterpret_cast<uint4*>(&Bhi[idx]) = *reinterpret_cast<const uint4*>(&g_wth[be]);
    *reinterpret_cast<uint4*>(&Bhi[idx + 8]) = *reinterpret_cast<const uint4*>(&g_wth[be + 8]);
    *reinterpret_cast<uint4*>(&Blo[idx]) = *reinterpret_cast<const uint4*>(&g_wtl[be]);
    *reinterpret_cast<uint4*>(&Blo[idx + 8]) = *reinterpret_cast<const uint4*>(&g_wtl[be + 8]);
}

// one 128x128x32 chunk stage (3-term split-bf16), ldmatrix + dependency-spread passes
// addresses are shared-space byte addresses of the four plane bases
__device__ __forceinline__ void mma_stage(
    uint32_t Ahi, uint32_t Alo, uint32_t Bhi, uint32_t Blo,
    int wm, int wn, int lane, float (*acc)[8][4])
{
    int aRow = lane & 15;
    uint32_t aColB = ((lane >> 4) & 1) * 16;     // +8 halves
    int bRow = (lane & 7) | (((lane >> 4) & 1) << 3);
    uint32_t bColB = ((lane >> 3) & 1) * 16;
    uint32_t aoff0 = (uint32_t)((wm * 32 + aRow) * 80) + aColB;
    uint32_t aoff1 = aoff0 + 16 * 80;
    uint32_t boff = (uint32_t)((wn * 64 + bRow) * 80) + bColB;
    #pragma unroll
    for (int ks = 0; ks < 2; ks++) {
        uint32_t kb = ks * 32;
        uint32_t ah[2][4], al[2][4];
        ldsm4(Ahi + aoff0 + kb, ah[0][0], ah[0][1], ah[0][2], ah[0][3]);
        ldsm4(Ahi + aoff1 + kb, ah[1][0], ah[1][1], ah[1][2], ah[1][3]);
        ldsm4(Alo + aoff0 + kb, al[0][0], al[0][1], al[0][2], al[0][3]);
        ldsm4(Alo + aoff1 + kb, al[1][0], al[1][1], al[1][2], al[1][3]);
        #pragma unroll
        for (int q = 0; q < 2; q++) {
            uint32_t nq = boff + (uint32_t)(q * 32 * 80) + kb;
            uint32_t bh[4][2], bl[4][2];
            ldsm4(Bhi + nq,           bh[0][0], bh[0][1], bh[1][0], bh[1][1]);
            ldsm4(Bhi + nq + 16 * 80, bh[2][0], bh[2][1], bh[3][0], bh[3][1]);
            ldsm4(Blo + nq,           bl[0][0], bl[0][1], bl[1][0], bl[1][1]);
            ldsm4(Blo + nq + 16 * 80, bl[2][0], bl[2][1], bl[3][0], bl[3][1]);
            #pragma unroll
            for (int j = 0; j < 4; j++) {
                mma_bf16(acc[0][q * 4 + j], ah[0], bh[j][0], bh[j][1]);
                mma_bf16(acc[1][q * 4 + j], ah[1], bh[j][0], bh[j][1]);
            }
            #pragma unroll
            for (int j = 0; j < 4; j++) {
                mma_bf16(acc[0][q * 4 + j], ah[0], bl[j][0], bl[j][1]);
                mma_bf16(acc[1][q * 4 + j], ah[1], bl[j][0], bl[j][1]);
            }
            #pragma unroll
            for (int j = 0; j < 4; j++) {
                mma_bf16(acc[0][q * 4 + j], al[0], bh[j][0], bh[j][1]);
                mma_bf16(acc[1][q * 4 + j], al[1], bh[j][0], bh[j][1]);
            }
        }
    }
}

// ---------------- batched layer-0 projection: msg_t = relu(x@Wp_t + bp_t) ----------------
#define SMEM_PROJ_BYTES (10 * CB)      // 102400
__global__ __launch_bounds__(256) void k_proj3(
    const float* __restrict__ x, const float* __restrict__ bp,
    float* __restrict__ m0, float* __restrict__ m1, float* __restrict__ m2)
{
    extern __shared__ __align__(16) char smem[];
    uint32_t sb = smem_u32(smem);
    __nv_bfloat16* Ahi = (__nv_bfloat16*)smem;      // 4 chunks resident
    __nv_bfloat16* Alo = Ahi + 4 * CH;
    __nv_bfloat16* Bhi = Alo + 4 * CH;
    __nv_bfloat16* Blo = Bhi + CH;

    int t = threadIdx.x, lane = t & 31, wid = t >> 5;
    int g = lane >> 2, tg = lane & 3;
    int wm = wid & 3, wn = wid >> 2;
    int row0 = blockIdx.x * 128;
    int ar = t >> 1, sel = t & 1;
    int kq = sel * 16;
    int gr = row0 + ar;
    bool valid = gr < N_NODES;

    // load full x tile (128x128) once
    #pragma unroll
    for (int c = 0; c < 4; c++)
        #pragma unroll
        for (int q = 0; q < 4; q++) {
            float4 v = valid ? *reinterpret_cast<const float4*>(&x[(size_t)gr * C + c * 32 + kq + q * 4])
                             : make_float4(0.f, 0.f, 0.f, 0.f);
            split_store4(Ahi, Alo, c * CH + ar * PITCH + kq + q * 4, v);
        }
    __syncthreads();

    float* msgs[3] = {m0, m1, m2};
    for (int tt = 0; tt < 3; tt++) {
        float acc[2][8][4];
        #pragma unroll
        for (int mi = 0; mi < 2; mi++)
            #pragma unroll
            for (int ni = 0; ni < 8; ni++)
                #pragma unroll
                for (int r = 0; r < 4; r++) acc[mi][ni][r] = 0.f;

        for (int s = 0; s < 4; s++) {
            load_B_planes(Bhi, Blo, tt, s * 32, ar, sel);
            __syncthreads();
            mma_stage(sb + s * CB, sb + 4 * CB + s * CB, sb + 8 * CB, sb + 9 * CB,
                      wm, wn, lane, acc);
            __syncthreads();
        }
        // epilogue: bias + relu -> msg_tt
        const float* bias = bp + tt * C;
        float* out = msgs[tt];
        #pragma unroll
        for (int mi = 0; mi < 2; mi++) {
            int r0 = row0 + wm * 32 + mi * 16 + g, r1 = r0 + 8;
            #pragma unroll
            for (int ni = 0; ni < 8; ni++) {
                int coln = wn * 64 + ni * 8 + tg * 2;
                float2 bv = *reinterpret_cast<const float2*>(&bias[coln]);
                float2 o0, o1;
                o0.x = fmaxf(acc[mi][ni][0] + bv.x, 0.f);
                o0.y = fmaxf(acc[mi][ni][1] + bv.y, 0.f);
                o1.x = fmaxf(acc[mi][ni][2] + bv.x, 0.f);
                o1.y = fmaxf(acc[mi][ni][3] + bv.y, 0.f);
                if (r0 < N_NODES) *reinterpret_cast<float2*>(&out[(size_t)r0 * C + coln]) = o0;
                if (r1 < N_NODES) *reinterpret_cast<float2*>(&out[(size_t)r1 * C + coln]) = o1;
            }
        }
    }
}

// ---------------- batched layer-0 dual GEMM + norm-accumulate + relu/3 + LN -> h ----------------
// no resident x (2 CTAs/SM): smem = A planes + B planes (40KB) + accum (67.5KB) + red
#define ACCP 132
#define SMEM_DUAL_BYTES (4 * CB + 128 * ACCP * 4 + 256 * 4 + 128 * 4)   // 110080
__global__ __launch_bounds__(256, 2) void k_dual0(
    const float* __restrict__ x,
    const float* __restrict__ a0, const float* __restrict__ a1, const float* __restrict__ a2,
    const float* __restrict__ bl0,
    const float* __restrict__ lng, const float* __restrict__ lnb,
    float* __restrict__ hout)
{
    extern __shared__ __align__(16) char smem[];
    uint32_t sb = smem_u32(smem);
    __nv_bfloat16* gAhi = (__nv_bfloat16*)smem;
    __nv_bfloat16* gAlo = gAhi + CH;
    __nv_bfloat16* Bhi  = gAlo + CH;
    __nv_bfloat16* Blo  = Bhi + CH;
    float* accum = (float*)(smem + 4 * CB);         // [128][ACCP]
    float* red   = accum + 128 * ACCP;              // [128][2]
    float* invn  = red + 256;                       // [128]

    int t = threadIdx.x, lane = t & 31, wid = t >> 5;
    int g = lane >> 2, tg = lane & 3;
    int wm = wid & 3, wn = wid >> 2;
    int row0 = blockIdx.x * 128;
    int ar = t >> 1, sel = t & 1;
    int kq = sel * 16;
    int gr = row0 + ar;
    bool valid = gr < N_NODES;

    // zero accum
    for (int i = t; i < 128 * ACCP; i += 256) accum[i] = 0.f;
    __syncthreads();

    const float* aggs[3] = {a0, a1, a2};
    for (int tt = 0; tt < 3; tt++) {
        float acc[2][8][4];
        #pragma unroll
        for (int mi = 0; mi < 2; mi++)
            #pragma unroll
            for (int ni = 0; ni < 8; ni++)
                #pragma unroll
                for (int r = 0; r < 4; r++) acc[mi][ni][r] = 0.f;

        // 8 stages per type: s<4 -> agg_t @ Wl0_t (mat 3+tt), s>=4 -> x @ Wr0_t (mat 6+tt)
        for (int s = 0; s < 8; s++) {
            const float* Ac = (s < 4) ? aggs[tt] : x;
            int mat = (s < 4) ? (3 + tt) : (6 + tt);
            int kc = (s & 3) * 32;
            #pragma unroll
            for (int q = 0; q < 4; q++) {
                float4 v = valid ? *reinterpret_cast<const float4*>(&Ac[(size_t)gr * C + kc + kq + q * 4])
                                 : make_float4(0.f, 0.f, 0.f, 0.f);
                split_store4(gAhi, gAlo, ar * PITCH + kq + q * 4, v);
            }
            load_B_planes(Bhi, Blo, mat, kc, ar, sel);
            __syncthreads();
            mma_stage(sb, sb + CB, sb + 2 * CB, sb + 3 * CB, wm, wn, lane, acc);
            __syncthreads();
        }
        // bias
        const float* bias = bl0 + tt * C;
        #pragma unroll
        for (int ni = 0; ni < 8; ni++) {
            int coln = wn * 64 + ni * 8 + tg * 2;
            float2 bv = *reinterpret_cast<const float2*>(&bias[coln]);
            #pragma unroll
            for (int mi = 0; mi < 2; mi++) {
                acc[mi][ni][0] += bv.x; acc[mi][ni][1] += bv.y;
                acc[mi][ni][2] += bv.x; acc[mi][ni][3] += bv.y;
            }
        }
        // per-row L2 norm
        float ss0[2] = {0.f, 0.f}, ss1[2] = {0.f, 0.f};
        #pragma unroll
        for (int mi = 0; mi < 2; mi++)
            #pragma unroll
            for (int ni = 0; ni < 8; ni++) {
                ss0[mi] += acc[mi][ni][0] * acc[mi][ni][0] + acc[mi][ni][1] * acc[mi][ni][1];
                ss1[mi] += acc[mi][ni][2] * acc[mi][ni][2] + acc[mi][ni][3] * acc[mi][ni][3];
            }
        #pragma unroll
        for (int mi = 0; mi < 2; mi++) {
            ss0[mi] += __shfl_xor_sync(0xffffffffu, ss0[mi], 1);
            ss0[mi] += __shfl_xor_sync(0xffffffffu, ss0[mi], 2);
            ss1[mi] += __shfl_xor_sync(0xffffffffu, ss1[mi], 1);
            ss1[mi] += __shfl_xor_sync(0xffffffffu, ss1[mi], 2);
        }
        if (tg == 0) {
            #pragma unroll
            for (int mi = 0; mi < 2; mi++) {
                red[(wm * 32 + mi * 16 + g) * 2 + wn] = ss0[mi];
                red[(wm * 32 + mi * 16 + 8 + g) * 2 + wn] = ss1[mi];
            }
        }
        __syncthreads();
        if (t < 128) invn[t] = 1.f / fmaxf(sqrtf(red[t * 2] + red[t * 2 + 1]), L2_EPS);
        __syncthreads();
        // accumulate normalized values into smem accum
        #pragma unroll
        for (int mi = 0; mi < 2; mi++) {
            int lr0 = wm * 32 + mi * 16 + g;
            float i0 = invn[lr0], i1 = invn[lr0 + 8];
            #pragma unroll
            for (int ni = 0; ni < 8; ni++) {
                int coln = wn * 64 + ni * 8 + tg * 2;
                accum[lr0 * ACCP + coln]       += acc[mi][ni][0] * i0;
                accum[lr0 * ACCP + coln + 1]   += acc[mi][ni][1] * i0;
                accum[(lr0 + 8) * ACCP + coln]     += acc[mi][ni][2] * i1;
                accum[(lr0 + 8) * ACCP + coln + 1] += acc[mi][ni][3] * i1;
            }
        }
        __syncthreads();
    }

    // final: h = LN(relu(accum/3))
    {
        int row = t >> 1, halfc = t & 1;
        int c0 = halfc * 64;
        float s = 0.f, q = 0.f;
        #pragma unroll
        for (int i = 0; i < 16; i++) {
            float4 v = *reinterpret_cast<float4*>(&accum[row * ACCP + c0 + i * 4]);
            v.x = fmaxf(v.x * (1.f / 3.f), 0.f);
            v.y = fmaxf(v.y * (1.f / 3.f), 0.f);
            v.z = fmaxf(v.z * (1.f / 3.f), 0.f);
            v.w = fmaxf(v.w * (1.f / 3.f), 0.f);
            s += v.x + v.y + v.z + v.w;
            q += v.x * v.x + v.y * v.y + v.z * v.z + v.w * v.w;
        }
        s += __shfl_xor_sync(0xffffffffu, s, 1);
        q += __shfl_xor_sync(0xffffffffu, q, 1);
        float mean = s * (1.f / 128.f);
        float var = q * (1.f / 128.f) - mean * mean;
        float rstd = rsqrtf(fmaxf(var, 0.f) + LN_EPS);
        int grow = row0 + row;
        if (grow < N_NODES) {
            #pragma unroll
            for (int i = 0; i < 16; i++) {
                float4 v = *reinterpret_cast<float4*>(&accum[row * ACCP + c0 + i * 4]);
                float4 gg = *reinterpret_cast<const float4*>(&lng[c0 + i * 4]);
                float4 bb = *reinterpret_cast<const float4*>(&lnb[c0 + i * 4]);
                float4 o;
                o.x = (fmaxf(v.x * (1.f / 3.f), 0.f) - mean) * rstd * gg.x + bb.x;
                o.y = (fmaxf(v.y * (1.f / 3.f), 0.f) - mean) * rstd * gg.y + bb.y;
                o.z = (fmaxf(v.z * (1.f / 3.f), 0.f) - mean) * rstd * gg.z + bb.z;
                o.w = (fmaxf(v.w * (1.f / 3.f), 0.f) - mean) * rstd * gg.w + bb.w;
                *reinterpret_cast<float4*>(&hout[(size_t)grow * C + c0 + i * 4]) = o;
            }
        }
    }
}

// ---------------- generic K=512 GEMM (layers 1..2) ----------------
// mode 2: out = (acc+bias)/3
// mode 3: out = LN(relu((acc+bias)/3))
#define SMEM_MMA_BYTES (4 * CB)    // 40960
__global__ __launch_bounds__(256, 2) void k_mma(
    const float* __restrict__ A0, const float* __restrict__ A1,
    const float* __restrict__ A2, const float* __restrict__ A3,
    int m0, int m1, int m2, int m3,
    const float* __restrict__ bias, const float* __restrict__ lng,
    const float* __restrict__ lnb, float* __restrict__ out, int mode)
{
    extern __shared__ __align__(16) char smem[];
    uint32_t sb = smem_u32(smem);
    __nv_bfloat16* Ahi = (__nv_bfloat16*)smem;
    __nv_bfloat16* Alo = Ahi + CH;
    __nv_bfloat16* Bhi = Alo + CH;
    __nv_bfloat16* Blo = Bhi + CH;

    int t = threadIdx.x, lane = t & 31, wid = t >> 5;
    int g = lane >> 2, tg = lane & 3;
    int wm = wid & 3, wn = wid >> 2;
    int row0 = blockIdx.x * 128;
    int ar = t >> 1, sel = t & 1;
    int kq = sel * 16;
    int gr = row0 + ar;
    bool valid = gr < N_NODES;

    const float* Aarr[4] = {A0, A1, A2, A3};
    int mats[4] = {m0, m1, m2, m3};

    float acc[2][8][4];
    #pragma unroll
    for (int mi = 0; mi < 2; mi++)
        #pragma unroll
        for (int ni = 0; ni < 8; ni++)
            #pragma unroll
            for (int r = 0; r < 4; r++) acc[mi][ni][r] = 0.f;

    for (int s = 0; s < 16; s++) {
        const float* Ac = Aarr[s >> 2];
        int kc = (s & 3) * 32;
        #pragma unroll
        for (int q = 0; q < 4; q++) {
            float4 v = valid ? *reinterpret_cast<const float4*>(&Ac[(size_t)gr * C + kc + kq + q * 4])
                             : make_float4(0.f, 0.f, 0.f, 0.f);
            split_store4(Ahi, Alo, ar * PITCH + kq + q * 4, v);
        }
        load_B_planes(Bhi, Blo, mats[s >> 2], kc, ar, sel);
        __syncthreads();
        mma_stage(sb, sb + CB, sb + 2 * CB, sb + 3 * CB, wm, wn, lane, acc);
        __syncthreads();
    }

    // bias + scale (+relu for mode 3)
    const float sc = 1.f / 3.f;
    #pragma unroll
    for (int ni = 0; ni < 8; ni++) {
        int coln = wn * 64 + ni * 8 + tg * 2;
        float2 bv = *reinterpret_cast<const float2*>(&bias[coln]);
        #pragma unroll
        for (int mi = 0; mi < 2; mi++) {
            acc[mi][ni][0] = (acc[mi][ni][0] + bv.x) * sc;
            acc[mi][ni][1] = (acc[mi][ni][1] + bv.y) * sc;
            acc[mi][ni][2] = (acc[mi][ni][2] + bv.x) * sc;
            acc[mi][ni][3] = (acc[mi][ni][3] + bv.y) * sc;
            if (mode == 3) {
                acc[mi][ni][0] = fmaxf(acc[mi][ni][0], 0.f);
                acc[mi][ni][1] = fmaxf(acc[mi][ni][1], 0.f);
                acc[mi][ni][2] = fmaxf(acc[mi][ni][2], 0.f);
                acc[mi][ni][3] = fmaxf(acc[mi][ni][3], 0.f);
            }
        }
    }

    if (mode == 3) {
        float* red_s = (float*)smem;     // [128][2]
        float* red_q = red_s + 256;      // [128][2]
        float* rmean = red_q + 256;      // [128]
        float* rstdv = rmean + 128;      // [128]
        float s0[2] = {0.f, 0.f}, q0[2] = {0.f, 0.f};
        float s1[2] = {0.f, 0.f}, q1[2] = {0.f, 0.f};
        #pragma unroll
        for (int mi = 0; mi < 2; mi++)
            #pragma unroll
            for (int ni = 0; ni < 8; ni++) {
                s0[mi] += acc[mi][ni][0] + acc[mi][ni][1];
                q0[mi] += acc[mi][ni][0] * acc[mi][ni][0] + acc[mi][ni][1] * acc[mi][ni][1];
                s1[mi] += acc[mi][ni][2] + acc[mi][ni][3];
                q1[mi] += acc[mi][ni][2] * acc[mi][ni][2] + acc[mi][ni][3] * acc[mi][ni][3];
            }
        #pragma unroll
        for (int mi = 0; mi < 2; mi++) {
            s0[mi] += __shfl_xor_sync(0xffffffffu, s0[mi], 1);
            s0[mi] += __shfl_xor_sync(0xffffffffu, s0[mi], 2);
            q0[mi] += __shfl_xor_sync(0xffffffffu, q0[mi], 1);
            q0[mi] += __shfl_xor_sync(0xffffffffu, q0[mi], 2);
            s1[mi] += __shfl_xor_sync(0xffffffffu, s1[mi], 1);
            s1[mi] += __shfl_xor_sync(0xffffffffu, s1[mi], 2);
            q1[mi] += __shfl_xor_sync(0xffffffffu, q1[mi], 1);
            q1[mi] += __shfl_xor_sync(0xffffffffu, q1[mi], 2);
        }
        if (tg == 0) {
            #pragma unroll
            for (int mi = 0; mi < 2; mi++) {
                int lr = wm * 32 + mi * 16 + g;
                red_s[lr * 2 + wn] = s0[mi];
                red_q[lr * 2 + wn] = q0[mi];
                red_s[(lr + 8) * 2 + wn] = s1[mi];
                red_q[(lr + 8) * 2 + wn] = q1[mi];
            }
        }
        __syncthreads();
        if (t < 128) {
            float ssum = red_s[t * 2] + red_s[t * 2 + 1];
            float qsum = red_q[t * 2] + red_q[t * 2 + 1];
            float mean = ssum * (1.f / 128.f);
            float var = qsum * (1.f / 128.f) - mean * mean;
            rmean[t] = mean;
            rstdv[t] = rsqrtf(fmaxf(var, 0.f) + LN_EPS);
        }
        __syncthreads();
        #pragma unroll
        for (int mi = 0; mi < 2; mi++) {
            int lr0 = wm * 32 + mi * 16 + g;
            int r0 = row0 + lr0, r1 = r0 + 8;
            float m0v = rmean[lr0], d0 = rstdv[lr0];
            float m1v = rmean[lr0 + 8], d1 = rstdv[lr0 + 8];
            #pragma unroll
            for (int ni = 0; ni < 8; ni++) {
                int coln = wn * 64 + ni * 8 + tg * 2;
                float2 gv = *reinterpret_cast<const float2*>(&lng[coln]);
                float2 bb = *reinterpret_cast<const float2*>(&lnb[coln]);
                if (r0 < N_NODES) {
                    float2 o;
                    o.x = (acc[mi][ni][0] - m0v) * d0 * gv.x + bb.x;
                    o.y = (acc[mi][ni][1] - m0v) * d0 * gv.y + bb.y;
                    *reinterpret_cast<float2*>(&out[(size_t)r0 * C + coln]) = o;
                }
                if (r1 < N_NODES) {
                    float2 o;
                    o.x = (acc[mi][ni][2] - m1v) * d1 * gv.x + bb.x;
                    o.y = (acc[mi][ni][3] - m1v) * d1 * gv.y + bb.y;
                    *reinterpret_cast<float2*>(&out[(size_t)r1 * C + coln]) = o;
                }
            }
        }
    } else {
        #pragma unroll
        for (int mi = 0; mi < 2; mi++) {
            int r0 = row0 + wm * 32 + mi * 16 + g, r1 = r0 + 8;
            #pragma unroll
            for (int ni = 0; ni < 8; ni++) {
                int coln = wn * 64 + ni * 8 + tg * 2;
                if (r0 < N_NODES) {
                    float2 o; o.x = acc[mi][ni][0]; o.y = acc[mi][ni][1];
                    *reinterpret_cast<float2*>(&out[(size_t)r0 * C + coln]) = o;
                }
                if (r1 < N_NODES) {
                    float2 o; o.x = acc[mi][ni][2]; o.y = acc[mi][ni][3];
                    *reinterpret_cast<float2*>(&out[(size_t)r1 * C + coln]) = o;
                }
            }
        }
    }
}

// ---------------- host orchestration ----------------
extern "C" void kernel_launch(void* const* d_in, const int* in_sizes, int n_in,
                              void* d_out, int out_size) {
    const float* x    = (const float*)d_in[0];
    const int*   edges = (const int*)d_in[1];
    const float* Wp   = (const float*)d_in[2];
    const float* bp   = (const float*)d_in[3];
    const float* Wl0  = (const float*)d_in[4];
    const float* bl0  = (const float*)d_in[5];
    const float* Wr0  = (const float*)d_in[6];
    const float* Wl   = (const float*)d_in[7];
    const float* bl   = (const float*)d_in[8];
    const float* Wr   = (const float*)d_in[9];
    const float* ln_g = (const float*)d_in[10];
    const float* ln_b = (const float*)d_in[11];
    float* out = (float*)d_out;

    void* p;
    float *msg0, *msg1, *msg2, *h, *agg0, *agg1, *agg2, *bsum;
    cudaGetSymbolAddress(&p, g_msg);  msg0 = (float*)p;
    cudaGetSymbolAddress(&p, g_accb); msg1 = (float*)p;
    cudaGetSymbolAddress(&p, g_h);    msg2 = (float*)p;  h = (float*)p;
    cudaGetSymbolAddress(&p, g_agg0); agg0 = (float*)p;
    cudaGetSymbolAddress(&p, g_agg1); agg1 = (float*)p;
    cudaGetSymbolAddress(&p, g_agg2); agg2 = (float*)p;
    cudaGetSymbolAddress(&p, g_bsum); bsum = (float*)p;

    cudaFuncSetAttribute(k_proj3, cudaFuncAttributeMaxDynamicSharedMemorySize, SMEM_PROJ_BYTES);
    cudaFuncSetAttribute(k_dual0, cudaFuncAttributeMaxDynamicSharedMemorySize, SMEM_DUAL_BYTES);
    cudaFuncSetAttribute(k_mma, cudaFuncAttributeMaxDynamicSharedMemorySize, SMEM_MMA_BYTES);

    int nbScan = (N_NODES + 1023) / 1024;
    dim3 gScan(nbScan, ET);
    int gMma = (N_NODES + 127) / 128;
    int gWarp = (N_NODES * 32 + 255) / 256;

    // launches 1-3: weight prep (independent of CSR)
    k_wsum<<<(2 * C * C + 255) / 256, 256>>>(Wr, bl);
    k_wprep<<<dim3(16, 17), dim3(32, 8)>>>(Wp, Wl0, Wr0, Wl);
    k_zero_int<<<(ET * N_NODES + 255) / 256, 256>>>();

    // launch 4 (ncu capture slot): the batched projection GEMM
    k_proj3<<<gMma, 256, SMEM_PROJ_BYTES>>>(x, bp, msg0, msg1, msg2);

    // CSR build
    k_hist<<<(ET * N_EDGES + 255) / 256, 256>>>(edges);
    k_scan1<<<gScan, 1024>>>();
    k_scan2<<<1, 32>>>();
    k_scan3<<<gScan, 1024>>>();
    k_invdeg<<<(ET * N_NODES + 255) / 256, 256>>>();
    k_scatter<<<(ET * N_EDGES + 255) / 256, 256>>>(edges);

    // layer 0 aggregation + dual GEMM (+ fused relu/3 + LN) -> h
    k_agg3<<<gWarp, 256>>>(msg0, msg1, msg2, agg0, agg1, agg2);
    k_dual0<<<gMma, 256, SMEM_DUAL_BYTES>>>(x, agg0, agg1, agg2, bl0, ln_g, ln_b, h);

    // layer 1: h = LN(relu((Σ agg@Wl + h@ΣWr + Σb)/3))
    k_agg3<<<gWarp, 256>>>(h, h, h, agg0, agg1, agg2);
    k_mma<<<gMma, 256, SMEM_MMA_BYTES>>>(agg0, agg1, agg2, h,
                           9, 10, 11, 15, bsum, ln_g + C, ln_b + C, h, 3);

    // layer 2: out = (Σ agg@Wl + h@ΣWr + Σb)/3
    k_agg3<<<gWarp, 256>>>(h, h, h, agg0, agg1, agg2);
    k_mma<<<gMma, 256, SMEM_MMA_BYTES>>>(agg0, agg1, agg2, h,
                           12, 13, 14, 16, bsum + C, ln_g, ln_b, out, 2);
}